// round 3
// baseline (speedup 1.0000x reference)
#include <cuda_runtime.h>
#include <math.h>

// ---------------------------------------------------------------------------
// simpleGNN: 2x GraphConv(128->128) + ReLU, segment_max pool, Linear(128->1),
// sigmoid.  Identity: segment_sum(x[src]*w) @ W == segment_sum((x@W)[src]*w),
// so GEMMs run first (dense, fast) and the scatter operates on projected rows.
//
// Index dtype is uncertain (reference asks for int64; JAX x64-disabled would
// deliver int32).  A device-side probe detects the layout and a conversion
// pass normalizes indices into int32 scratch, so hot kernels are branch-free.
// ---------------------------------------------------------------------------

#define MAX_NODES 50000
#define MAX_EDGES 640000
#define FDIM      128

__device__ float g_Z    [MAX_NODES * FDIM];
__device__ float g_H1   [MAX_NODES * FDIM];
__device__ float g_H2   [MAX_NODES * FDIM];
__device__ int   g_ei   [2 * MAX_EDGES];
__device__ int   g_batch[MAX_NODES];
__device__ int   g_idx64;

// ---------------------------------------------------------------------------
// Probe: for int64 data (little-endian), odd 32-bit words are the high halves
// of values < 50000 -> all zero.  For int32 data, 64 consecutive random node
// ids all being zero has probability ~(1/50000)^64.
// ---------------------------------------------------------------------------
__global__ void detect_kernel(const int* __restrict__ ei)
{
    int is64 = 1;
    for (int k = 1; k < 128; k += 2)
        if (ei[k] != 0) { is64 = 0; break; }
    g_idx64 = is64;
}

// Normalize edge_index [2E] and batch [N] to int32 scratch.
__global__ void convert_kernel(const int* __restrict__ ei,
                               const int* __restrict__ batch,
                               int twoE, int Nn)
{
    int i = blockIdx.x * blockDim.x + threadIdx.x;
    int f = g_idx64;
    if (i < twoE) g_ei[i]    = f ? ei[2 * i]    : ei[i];
    if (i < Nn)   g_batch[i] = f ? batch[2 * i] : batch[i];
}

// ---------------------------------------------------------------------------
// Dual-output SGEMM:  Z[m,:] = act(A[m,:]) @ Wrel ; H[m,:] = act(A[m,:]) @ Wroot + bias
// A: [M,128] row-major.  Wrel/Wroot: [128,128] row-major.
// Block tile 64x64, K-tile 16, thread tile 4x4, 256 threads.
// grid = (ceil(M/64), 4)   (global cols 0..255; col>=128 -> root half)
// ---------------------------------------------------------------------------
template<bool RELU>
__global__ void __launch_bounds__(256)
gemm_dual(const float* __restrict__ A,
          const float* __restrict__ Wrel,
          const float* __restrict__ Wroot,
          const float* __restrict__ bias,
          float* __restrict__ Z,
          float* __restrict__ H,
          int M)
{
    const int BM = 64, BN = 64, BK = 16;
    __shared__ float As[BK][BM];   // As[k][m]
    __shared__ float Bs[BK][BN];   // Bs[k][n]

    const int tid = threadIdx.x;        // 0..255
    const int tx  = tid & 15;           // col group
    const int ty  = tid >> 4;           // row group
    const int row0 = blockIdx.x * BM;
    const int col0 = blockIdx.y * BN;   // 0,64,128,192

    float acc[4][4] = {};

    for (int k0 = 0; k0 < 128; k0 += BK) {
        #pragma unroll
        for (int i = tid; i < BM * BK; i += 256) {
            int m = i >> 4;
            int k = i & 15;
            int r = row0 + m;
            float a = (r < M) ? A[(size_t)r * 128 + k0 + k] : 0.0f;
            if (RELU) a = fmaxf(a, 0.0f);
            As[k][m] = a;
        }
        #pragma unroll
        for (int i = tid; i < BK * BN; i += 256) {
            int k  = i >> 6;
            int n  = i & 63;
            int gn = col0 + n;
            float b = (gn < 128) ? Wrel [(k0 + k) * 128 + gn]
                                 : Wroot[(k0 + k) * 128 + gn - 128];
            Bs[k][n] = b;
        }
        __syncthreads();

        #pragma unroll
        for (int k = 0; k < BK; k++) {
            float4 a4 = *(const float4*)&As[k][ty * 4];
            float4 b4 = *(const float4*)&Bs[k][tx * 4];
            float a[4] = {a4.x, a4.y, a4.z, a4.w};
            float b[4] = {b4.x, b4.y, b4.z, b4.w};
            #pragma unroll
            for (int i = 0; i < 4; i++)
                #pragma unroll
                for (int j = 0; j < 4; j++)
                    acc[i][j] = fmaf(a[i], b[j], acc[i][j]);
        }
        __syncthreads();
    }

    #pragma unroll
    for (int i = 0; i < 4; i++) {
        int r = row0 + ty * 4 + i;
        if (r >= M) continue;
        #pragma unroll
        for (int j = 0; j < 4; j++) {
            int gn = col0 + tx * 4 + j;
            if (gn < 128) {
                Z[(size_t)r * 128 + gn] = acc[i][j];
            } else {
                H[(size_t)r * 128 + gn - 128] = acc[i][j] + bias[gn - 128];
            }
        }
    }
}

// ---------------------------------------------------------------------------
// Edge scatter: one warp per edge.  lane loads float4 of Z[src], scales by w,
// vector-atomicAdd into H[dst].  32 lanes x float4 = 128 floats.
// Out-of-range guard degrades to wrong-answer, never a crash.
// ---------------------------------------------------------------------------
__global__ void __launch_bounds__(256)
scatter_add(const float* __restrict__ Z,
            float* __restrict__ H,
            const int* __restrict__ ei,   // normalized [2,E]: src rows then dst rows
            const float* __restrict__ ew,
            int E, int Nn)
{
    int gw   = (int)((blockIdx.x * (unsigned)blockDim.x + threadIdx.x) >> 5);
    int lane = threadIdx.x & 31;
    if (gw >= E) return;

    int s = ei[gw];
    int d = ei[E + gw];
    if ((unsigned)s >= (unsigned)Nn || (unsigned)d >= (unsigned)Nn) return;
    float w = ew[gw];

    float4 v = ((const float4*)(Z + (size_t)s * 128))[lane];
    v.x *= w; v.y *= w; v.z *= w; v.w *= w;
    atomicAdd(((float4*)(H + (size_t)d * 128)) + lane, v);
}

// ---------------------------------------------------------------------------
// Pool: one block per graph.  batch sorted -> binary search the node range.
// Per-feature max of relu(H2), dot with W_lin, +b, sigmoid.
// ---------------------------------------------------------------------------
__global__ void __launch_bounds__(128)
pool_kernel(const float* __restrict__ H2,
            const int* __restrict__ batch,  // normalized int32
            const float* __restrict__ Wlin,
            const float* __restrict__ blin,
            float* __restrict__ out,
            int Nn)
{
    int g = blockIdx.x;
    int t = threadIdx.x;   // 128 threads, thread t owns feature t

    __shared__ int s_range[2];
    if (t < 2) {
        int target = g + t;
        int lo = 0, hi = Nn;
        while (lo < hi) {
            int mid = (lo + hi) >> 1;
            if (batch[mid] < target) lo = mid + 1; else hi = mid;
        }
        s_range[t] = lo;
    }
    __syncthreads();
    int lo = s_range[0], hi = s_range[1];

    float m = -INFINITY;
    for (int n = lo; n < hi; n++)
        m = fmaxf(m, H2[(size_t)n * 128 + t]);
    if (hi > lo) m = fmaxf(m, 0.0f);   // relu-before-max == clamp of max (nonempty)

    float v = m * Wlin[t];

    __shared__ float red[128];
    red[t] = v;
    __syncthreads();
    #pragma unroll
    for (int s = 64; s > 0; s >>= 1) {
        if (t < s) red[t] += red[t + s];
        __syncthreads();
    }
    if (t == 0) {
        float logit = red[0] + blin[0];
        out[g] = 1.0f / (1.0f + expf(-logit));
    }
}

// ---------------------------------------------------------------------------
extern "C" void kernel_launch(void* const* d_in, const int* in_sizes, int n_in,
                              void* d_out, int out_size)
{
    const float* x      = (const float*) d_in[0];
    const int*   ei     = (const int*)   d_in[1];
    const int*   batch  = (const int*)   d_in[2];
    const float* ew     = (const float*) d_in[3];
    const float* W1rel  = (const float*) d_in[4];
    const float* b1     = (const float*) d_in[5];
    const float* W1root = (const float*) d_in[6];
    const float* W2rel  = (const float*) d_in[7];
    const float* b2     = (const float*) d_in[8];
    const float* W2root = (const float*) d_in[9];
    const float* Wlin   = (const float*) d_in[10];
    const float* blin   = (const float*) d_in[11];
    float* out = (float*)d_out;

    int M = in_sizes[0] / 128;   // nodes
    int E = in_sizes[1] / 2;     // edges
    int G = out_size;            // graphs
    if (M > MAX_NODES) M = MAX_NODES;
    if (E > MAX_EDGES) E = MAX_EDGES;

    float *Z, *H1, *H2;
    int *eiN, *batchN;
    cudaGetSymbolAddress((void**)&Z,      g_Z);
    cudaGetSymbolAddress((void**)&H1,     g_H1);
    cudaGetSymbolAddress((void**)&H2,     g_H2);
    cudaGetSymbolAddress((void**)&eiN,    g_ei);
    cudaGetSymbolAddress((void**)&batchN, g_batch);

    // Normalize index dtype (int64 vs int32) into int32 scratch.
    detect_kernel<<<1, 1>>>(ei);
    {
        int work = 2 * E;
        if (M > work) work = M;
        convert_kernel<<<(work + 255) / 256, 256>>>(ei, batch, 2 * E, M);
    }

    dim3 ggrid((M + 63) / 64, 4);

    // Layer 1: Z = x@W1rel ; H1 = x@W1root + b1
    gemm_dual<false><<<ggrid, 256>>>(x, W1rel, W1root, b1, Z, H1, M);
    {
        long long threads = (long long)E * 32;
        int blocks = (int)((threads + 255) / 256);
        scatter_add<<<blocks, 256>>>(Z, H1, eiN, ew, E, M);
    }
    // Layer 2: Z = relu(H1)@W2rel ; H2 = relu(H1)@W2root + b2
    gemm_dual<true><<<ggrid, 256>>>(H1, W2rel, W2root, b2, Z, H2, M);
    {
        long long threads = (long long)E * 32;
        int blocks = (int)((threads + 255) / 256);
        scatter_add<<<blocks, 256>>>(Z, H2, eiN, ew, E, M);
    }
    // Pool + linear + sigmoid
    pool_kernel<<<G, 128>>>(H2, batchN, Wlin, blin, out, M);
}

// round 4
// speedup vs baseline: 1.0890x; 1.0890x over previous
#include <cuda_runtime.h>
#include <math.h>

// ---------------------------------------------------------------------------
// simpleGNN: 2x GraphConv(128->128) + ReLU, segment_max pool, Linear(128->1),
// sigmoid.
// Identity: segment_sum(x[src]*w) @ W == segment_sum((x@W)[src]*w) -> GEMM
// first, scatter projected rows.
// R4: (a) GEMM inner loop uses packed fma.rn.f32x2 (2x fp32 FMA throughput),
//     (b) atomic scatter replaced by CSR build + warp-per-node register
//         accumulation (no float atomics).
// ---------------------------------------------------------------------------

#define MAX_NODES 50000
#define MAX_EDGES 640000
#define FDIM      128

typedef unsigned long long u64;

__device__ float g_Z    [MAX_NODES * FDIM];
__device__ float g_H1   [MAX_NODES * FDIM];
__device__ float g_H2   [MAX_NODES * FDIM];
__device__ int   g_ei   [2 * MAX_EDGES];
__device__ int   g_batch[MAX_NODES];
__device__ int   g_idx64;
// CSR scratch
__device__ int   g_deg  [MAX_NODES];      // histogram, then fill-cursor
__device__ int   g_off  [MAX_NODES + 1];
__device__ int   g_src  [MAX_EDGES];
__device__ float g_wp   [MAX_EDGES];

// ---------------- packed f32x2 helpers -------------------------------------
__device__ __forceinline__ u64 fma2(u64 a, u64 b, u64 c) {
    u64 d;
    asm("fma.rn.f32x2 %0, %1, %2, %3;" : "=l"(d) : "l"(a), "l"(b), "l"(c));
    return d;
}
__device__ __forceinline__ u64 pack_dup(float x) {
    u64 d;
    asm("mov.b64 %0, {%1, %1};" : "=l"(d) : "f"(x));
    return d;
}
__device__ __forceinline__ float2 unpack2(u64 p) {
    float2 f;
    asm("mov.b64 {%0, %1}, %2;" : "=f"(f.x), "=f"(f.y) : "l"(p));
    return f;
}

// ---------------------------------------------------------------------------
// Index-dtype probe: for int64 little-endian data the odd 32-bit words (high
// halves of values < 50000) are all zero; for int32 random node ids, 64
// consecutive zeros is impossible in practice.
// ---------------------------------------------------------------------------
__global__ void detect_kernel(const int* __restrict__ ei)
{
    int is64 = 1;
    for (int k = 1; k < 128; k += 2)
        if (ei[k] != 0) { is64 = 0; break; }
    g_idx64 = is64;
}

// Normalize edge_index/batch to int32 scratch; also zero the degree array.
__global__ void convert_kernel(const int* __restrict__ ei,
                               const int* __restrict__ batch,
                               int twoE, int Nn)
{
    int i = blockIdx.x * blockDim.x + threadIdx.x;
    int f = g_idx64;
    if (i < twoE) g_ei[i]    = f ? ei[2 * i]    : ei[i];
    if (i < Nn) {
        g_batch[i] = f ? batch[2 * i] : batch[i];
        g_deg[i]   = 0;
    }
}

// ---------------------------------------------------------------------------
// CSR build: histogram -> single-block scan -> fill
// ---------------------------------------------------------------------------
__global__ void hist_kernel(int E, int Nn)
{
    int i = blockIdx.x * blockDim.x + threadIdx.x;
    if (i >= E) return;
    int d = g_ei[E + i];
    if ((unsigned)d < (unsigned)Nn) atomicAdd(&g_deg[d], 1);
}

__global__ void __launch_bounds__(1024)
scan_kernel(int Nn)
{
    __shared__ int sums[1024];
    int t = threadIdx.x;
    int chunk = (Nn + 1023) / 1024;
    int lo = t * chunk;
    int hi = lo + chunk; if (hi > Nn) hi = Nn;
    if (lo > Nn) lo = Nn;

    int s = 0;
    for (int i = lo; i < hi; i++) s += g_deg[i];
    sums[t] = s;
    __syncthreads();
    // inclusive Hillis-Steele scan
    for (int d = 1; d < 1024; d <<= 1) {
        int v = (t >= d) ? sums[t - d] : 0;
        __syncthreads();
        sums[t] += v;
        __syncthreads();
    }
    int run = (t == 0) ? 0 : sums[t - 1];
    for (int i = lo; i < hi; i++) {
        int d = g_deg[i];
        g_off[i] = run;
        g_deg[i] = run;   // cursor for fill pass
        run += d;
    }
    if (t == 1023) g_off[Nn] = sums[1023];
}

__global__ void fill_kernel(const float* __restrict__ ew, int E, int Nn)
{
    int i = blockIdx.x * blockDim.x + threadIdx.x;
    if (i >= E) return;
    int s = g_ei[i];
    int d = g_ei[E + i];
    if ((unsigned)s >= (unsigned)Nn || (unsigned)d >= (unsigned)Nn) return;
    int p = atomicAdd(&g_deg[d], 1);
    g_src[p] = s;
    g_wp[p]  = ew[i];
}

// ---------------------------------------------------------------------------
// Dual-output SGEMM with packed f32x2 FMA.
//   Z[m,:] = act(A[m,:]) @ Wrel ;  H[m,:] = act(A[m,:]) @ Wroot + bias
// Block tile 128x64, BK=16, 256 threads, thread tile 8 rows x 4 cols.
// B values are duplicated into f32x2 pairs in smem so the inner loop is pure
// fma.rn.f32x2 (row-pairs of A x dup-B).
// grid = (ceil(M/128), 4); blockIdx.y>=2 -> root half (cols 128..255).
// ---------------------------------------------------------------------------
template<bool RELU>
__global__ void __launch_bounds__(256)
gemm_dual(const float* __restrict__ A,
          const float* __restrict__ Wrel,
          const float* __restrict__ Wroot,
          const float* __restrict__ bias,
          float* __restrict__ Z,
          float* __restrict__ H,
          int M)
{
    const int BM = 128, BN = 64, BK = 16;
    __shared__ __align__(16) float As[BK][BM];
    __shared__ __align__(16) u64   Bs[BK][BN];   // duplicated pairs

    const int tid = threadIdx.x;
    const int tx  = tid & 15;            // col group: 4 cols
    const int ty  = tid >> 4;            // row group: 8 rows
    const int row0 = blockIdx.x * BM;
    const int col0 = blockIdx.y * BN;    // 0,64,128,192

    u64 acc[4][4];
    #pragma unroll
    for (int i = 0; i < 4; i++)
        #pragma unroll
        for (int j = 0; j < 4; j++) acc[i][j] = 0ull;

    for (int k0 = 0; k0 < 128; k0 += BK) {
        // A tile: 128 rows x 16 k, via float4 (512 float4, 2 per thread)
        #pragma unroll
        for (int i = tid; i < 512; i += 256) {
            int r  = i >> 2;
            int kq = i & 3;
            int gr = row0 + r;
            float4 a = make_float4(0.f, 0.f, 0.f, 0.f);
            if (gr < M) a = *(const float4*)(A + (size_t)gr * 128 + k0 + kq * 4);
            if (RELU) {
                a.x = fmaxf(a.x, 0.f); a.y = fmaxf(a.y, 0.f);
                a.z = fmaxf(a.z, 0.f); a.w = fmaxf(a.w, 0.f);
            }
            As[kq * 4 + 0][r] = a.x;
            As[kq * 4 + 1][r] = a.y;
            As[kq * 4 + 2][r] = a.z;
            As[kq * 4 + 3][r] = a.w;
        }
        // B tile: 16 k x 64 cols, duplicated pairs
        #pragma unroll
        for (int i = tid; i < BK * BN; i += 256) {
            int k  = i >> 6;
            int n  = i & 63;
            int gn = col0 + n;
            float b = (gn < 128) ? Wrel [(k0 + k) * 128 + gn]
                                 : Wroot[(k0 + k) * 128 + gn - 128];
            Bs[k][n] = pack_dup(b);
        }
        __syncthreads();

        #pragma unroll
        for (int k = 0; k < BK; k++) {
            const ulonglong2* ap = (const ulonglong2*)&As[k][ty * 8];
            ulonglong2 a01 = ap[0];
            ulonglong2 a23 = ap[1];
            const ulonglong2* bp = (const ulonglong2*)&Bs[k][tx * 4];
            ulonglong2 b01 = bp[0];
            ulonglong2 b23 = bp[1];
            u64 av[4] = {a01.x, a01.y, a23.x, a23.y};
            u64 bv[4] = {b01.x, b01.y, b23.x, b23.y};
            #pragma unroll
            for (int i = 0; i < 4; i++)
                #pragma unroll
                for (int j = 0; j < 4; j++)
                    acc[i][j] = fma2(av[i], bv[j], acc[i][j]);
        }
        __syncthreads();
    }

    // Epilogue: 8 rows x 4 cols per thread, float4 stores per row.
    const int gn0 = col0 + tx * 4;
    const bool relHalf = (gn0 < 128);
    float4 bv4 = make_float4(0.f, 0.f, 0.f, 0.f);
    if (!relHalf) bv4 = *(const float4*)(bias + gn0 - 128);

    #pragma unroll
    for (int rp = 0; rp < 4; rp++) {
        float2 f0 = unpack2(acc[rp][0]);
        float2 f1 = unpack2(acc[rp][1]);
        float2 f2 = unpack2(acc[rp][2]);
        float2 f3 = unpack2(acc[rp][3]);
        int r0 = row0 + ty * 8 + rp * 2;
        int r1 = r0 + 1;
        if (relHalf) {
            if (r0 < M) *(float4*)(Z + (size_t)r0 * 128 + gn0) =
                make_float4(f0.x, f1.x, f2.x, f3.x);
            if (r1 < M) *(float4*)(Z + (size_t)r1 * 128 + gn0) =
                make_float4(f0.y, f1.y, f2.y, f3.y);
        } else {
            int c0 = gn0 - 128;
            if (r0 < M) *(float4*)(H + (size_t)r0 * 128 + c0) =
                make_float4(f0.x + bv4.x, f1.x + bv4.y, f2.x + bv4.z, f3.x + bv4.w);
            if (r1 < M) *(float4*)(H + (size_t)r1 * 128 + c0) =
                make_float4(f0.y + bv4.x, f1.y + bv4.y, f2.y + bv4.z, f3.y + bv4.w);
        }
    }
}

// ---------------------------------------------------------------------------
// CSR gather: one warp per dst node.  Lane owns float4 of the 128-wide row.
// Accumulate all incoming edges in registers, single RMW of H (no atomics).
// ---------------------------------------------------------------------------
__global__ void __launch_bounds__(256)
gather_kernel(const float* __restrict__ Z,
              float* __restrict__ H,
              int Nn)
{
    int warp = (int)((blockIdx.x * (unsigned)blockDim.x + threadIdx.x) >> 5);
    int lane = threadIdx.x & 31;
    if (warp >= Nn) return;

    int lo = g_off[warp];
    int hi = g_off[warp + 1];
    if (lo == hi) return;

    float4 acc = make_float4(0.f, 0.f, 0.f, 0.f);
    int e = lo;
    // 2-way unroll for memory-level parallelism
    for (; e + 1 < hi; e += 2) {
        int   s0 = g_src[e],     s1 = g_src[e + 1];
        float w0 = g_wp[e],      w1 = g_wp[e + 1];
        float4 v0 = ((const float4*)(Z + (size_t)s0 * 128))[lane];
        float4 v1 = ((const float4*)(Z + (size_t)s1 * 128))[lane];
        acc.x = fmaf(w0, v0.x, acc.x); acc.y = fmaf(w0, v0.y, acc.y);
        acc.z = fmaf(w0, v0.z, acc.z); acc.w = fmaf(w0, v0.w, acc.w);
        acc.x = fmaf(w1, v1.x, acc.x); acc.y = fmaf(w1, v1.y, acc.y);
        acc.z = fmaf(w1, v1.z, acc.z); acc.w = fmaf(w1, v1.w, acc.w);
    }
    if (e < hi) {
        int   s0 = g_src[e];
        float w0 = g_wp[e];
        float4 v0 = ((const float4*)(Z + (size_t)s0 * 128))[lane];
        acc.x = fmaf(w0, v0.x, acc.x); acc.y = fmaf(w0, v0.y, acc.y);
        acc.z = fmaf(w0, v0.z, acc.z); acc.w = fmaf(w0, v0.w, acc.w);
    }

    float4* hp = ((float4*)(H + (size_t)warp * 128)) + lane;
    float4 h = *hp;
    h.x += acc.x; h.y += acc.y; h.z += acc.z; h.w += acc.w;
    *hp = h;
}

// ---------------------------------------------------------------------------
// Pool: one block per graph (batch sorted -> binary search range).
// Per-feature max of relu(H2), dot with W_lin, +b, sigmoid.
// ---------------------------------------------------------------------------
__global__ void __launch_bounds__(128)
pool_kernel(const float* __restrict__ H2,
            const float* __restrict__ Wlin,
            const float* __restrict__ blin,
            float* __restrict__ out,
            int Nn)
{
    int g = blockIdx.x;
    int t = threadIdx.x;

    __shared__ int s_range[2];
    if (t < 2) {
        int target = g + t;
        int lo = 0, hi = Nn;
        while (lo < hi) {
            int mid = (lo + hi) >> 1;
            if (g_batch[mid] < target) lo = mid + 1; else hi = mid;
        }
        s_range[t] = lo;
    }
    __syncthreads();
    int lo = s_range[0], hi = s_range[1];

    float m = -INFINITY;
    for (int n = lo; n < hi; n++)
        m = fmaxf(m, H2[(size_t)n * 128 + t]);
    if (hi > lo) m = fmaxf(m, 0.0f);   // relu-before-max == clamp of max

    float v = m * Wlin[t];

    __shared__ float red[128];
    red[t] = v;
    __syncthreads();
    #pragma unroll
    for (int s = 64; s > 0; s >>= 1) {
        if (t < s) red[t] += red[t + s];
        __syncthreads();
    }
    if (t == 0) {
        float logit = red[0] + blin[0];
        out[g] = 1.0f / (1.0f + expf(-logit));
    }
}

// ---------------------------------------------------------------------------
extern "C" void kernel_launch(void* const* d_in, const int* in_sizes, int n_in,
                              void* d_out, int out_size)
{
    const float* x      = (const float*) d_in[0];
    const int*   ei     = (const int*)   d_in[1];
    const int*   batch  = (const int*)   d_in[2];
    const float* ew     = (const float*) d_in[3];
    const float* W1rel  = (const float*) d_in[4];
    const float* b1     = (const float*) d_in[5];
    const float* W1root = (const float*) d_in[6];
    const float* W2rel  = (const float*) d_in[7];
    const float* b2     = (const float*) d_in[8];
    const float* W2root = (const float*) d_in[9];
    const float* Wlin   = (const float*) d_in[10];
    const float* blin   = (const float*) d_in[11];
    float* out = (float*)d_out;

    int M = in_sizes[0] / 128;   // nodes
    int E = in_sizes[1] / 2;     // edges
    int G = out_size;            // graphs
    if (M > MAX_NODES) M = MAX_NODES;
    if (E > MAX_EDGES) E = MAX_EDGES;

    float *Z, *H1, *H2;
    cudaGetSymbolAddress((void**)&Z,  g_Z);
    cudaGetSymbolAddress((void**)&H1, g_H1);
    cudaGetSymbolAddress((void**)&H2, g_H2);

    // Normalize index dtype + zero degree histogram.
    detect_kernel<<<1, 1>>>(ei);
    {
        int work = 2 * E;
        if (M > work) work = M;
        convert_kernel<<<(work + 255) / 256, 256>>>(ei, batch, 2 * E, M);
    }
    // CSR build (indices/weights static per call).
    hist_kernel<<<(E + 255) / 256, 256>>>(E, M);
    scan_kernel<<<1, 1024>>>(M);
    fill_kernel<<<(E + 255) / 256, 256>>>(ew, E, M);

    dim3 ggrid((M + 127) / 128, 4);
    int gatherBlocks = (M * 32 + 255) / 256;

    // Layer 1
    gemm_dual<false><<<ggrid, 256>>>(x, W1rel, W1root, b1, Z, H1, M);
    gather_kernel<<<gatherBlocks, 256>>>(Z, H1, M);
    // Layer 2
    gemm_dual<true><<<ggrid, 256>>>(H1, W2rel, W2root, b2, Z, H2, M);
    gather_kernel<<<gatherBlocks, 256>>>(Z, H2, M);
    // Pool + linear + sigmoid
    pool_kernel<<<G, 128>>>(H2, Wlin, blin, out, M);
}

// round 6
// speedup vs baseline: 1.2841x; 1.1792x over previous
#include <cuda_runtime.h>
#include <math.h>

// ---------------------------------------------------------------------------
// simpleGNN: 2x GraphConv(128->128) + ReLU, segment_max pool, Linear(128->1),
// sigmoid.
// Identity: segment_sum(x[src]*w) @ W == segment_sum((x@W)[src]*w) -> GEMM
// first, gather projected rows per dst node (CSR, no float atomics).
// R6 == R5 (infra failure last round) + 4-way unrolled gather loop:
//   parallel CSR build (blocked scan), hist+detect fused into convert,
//   degree-array zeroing folded into pool.
// ---------------------------------------------------------------------------

#define MAX_NODES 50000
#define MAX_EDGES 640000
#define FDIM      128
#define SCAN_CHUNK 1024            // deg entries per scan block
#define MAX_PARTS  64              // ceil(MAX_NODES/SCAN_CHUNK) <= 64

typedef unsigned long long u64;

__device__ float g_Z    [MAX_NODES * FDIM];
__device__ float g_H1   [MAX_NODES * FDIM];
__device__ float g_H2   [MAX_NODES * FDIM];
__device__ int   g_ei   [2 * MAX_EDGES];
__device__ int   g_batch[MAX_NODES];
// CSR scratch
__device__ int   g_deg  [MAX_NODES];      // histogram, then fill-cursor; zeroed by pool
__device__ int   g_off  [MAX_NODES + 1];
__device__ int   g_part [MAX_PARTS];
__device__ int   g_src  [MAX_EDGES];
__device__ float g_wp   [MAX_EDGES];

// ---------------- packed f32x2 helpers -------------------------------------
__device__ __forceinline__ u64 fma2(u64 a, u64 b, u64 c) {
    u64 d;
    asm("fma.rn.f32x2 %0, %1, %2, %3;" : "=l"(d) : "l"(a), "l"(b), "l"(c));
    return d;
}
__device__ __forceinline__ u64 pack_dup(float x) {
    u64 d;
    asm("mov.b64 %0, {%1, %1};" : "=l"(d) : "f"(x));
    return d;
}
__device__ __forceinline__ float2 unpack2(u64 p) {
    float2 f;
    asm("mov.b64 {%0, %1}, %2;" : "=f"(f.x), "=f"(f.y) : "l"(p));
    return f;
}

// ---------------------------------------------------------------------------
// convert + histogram + dtype detect (fused).
// int64 LE data: odd 32-bit words of values < 50000 are all zero.  Each block
// detects independently.  Threads in [E,2E) also histogram dst into g_deg.
// ---------------------------------------------------------------------------
__global__ void __launch_bounds__(256)
convert_hist(const int* __restrict__ ei,
             const int* __restrict__ batch,
             int E, int Nn)
{
    __shared__ int s_is64;
    if (threadIdx.x == 0) {
        int any = 0;
        #pragma unroll
        for (int k = 1; k < 128; k += 2) any |= ei[k];
        s_is64 = (any == 0);
    }
    __syncthreads();
    int f = s_is64;

    int i = blockIdx.x * blockDim.x + threadIdx.x;
    int twoE = 2 * E;
    if (i < twoE) {
        int v = f ? ei[2 * i] : ei[i];
        g_ei[i] = v;
        if (i >= E && (unsigned)v < (unsigned)Nn)
            atomicAdd(&g_deg[v], 1);
    }
    if (i < Nn)
        g_batch[i] = f ? batch[2 * i] : batch[i];
}

// ---------------------------------------------------------------------------
// Blocked exclusive scan of g_deg -> g_off (3 kernels, all parallel).
// ---------------------------------------------------------------------------
__global__ void __launch_bounds__(256)
partial_kernel(int Nn)
{
    __shared__ int red[256];
    int t = threadIdx.x;
    int base = blockIdx.x * SCAN_CHUNK + t * 4;
    int s = 0;
    #pragma unroll
    for (int j = 0; j < 4; j++) {
        int idx = base + j;
        s += (idx < Nn) ? g_deg[idx] : 0;
    }
    red[t] = s;
    __syncthreads();
    #pragma unroll
    for (int d = 128; d > 0; d >>= 1) {
        if (t < d) red[t] += red[t + d];
        __syncthreads();
    }
    if (t == 0) g_part[blockIdx.x] = red[0];
}

__global__ void __launch_bounds__(64)
scan_part_kernel(int NB, int Nn)
{
    __shared__ int s[MAX_PARTS];
    int t = threadIdx.x;
    s[t] = (t < NB) ? g_part[t] : 0;
    __syncthreads();
    #pragma unroll
    for (int d = 1; d < MAX_PARTS; d <<= 1) {
        int v = (t >= d) ? s[t - d] : 0;
        __syncthreads();
        s[t] += v;
        __syncthreads();
    }
    if (t < NB) g_part[t] = (t == 0) ? 0 : s[t - 1];   // exclusive
    if (t == MAX_PARTS - 1) g_off[Nn] = s[MAX_PARTS - 1];
}

__global__ void __launch_bounds__(256)
writeoff_kernel(int Nn)
{
    __shared__ int sums[256];
    int t = threadIdx.x;
    int base = blockIdx.x * SCAN_CHUNK + t * 4;

    int local[4];
    int s = 0;
    #pragma unroll
    for (int j = 0; j < 4; j++) {
        int idx = base + j;
        local[j] = (idx < Nn) ? g_deg[idx] : 0;
        s += local[j];
    }
    sums[t] = s;
    __syncthreads();
    // Hillis-Steele inclusive over 256 thread sums
    #pragma unroll
    for (int d = 1; d < 256; d <<= 1) {
        int v = (t >= d) ? sums[t - d] : 0;
        __syncthreads();
        sums[t] += v;
        __syncthreads();
    }
    int run = g_part[blockIdx.x] + ((t == 0) ? 0 : sums[t - 1]);
    #pragma unroll
    for (int j = 0; j < 4; j++) {
        int idx = base + j;
        if (idx < Nn) {
            g_off[idx] = run;
            g_deg[idx] = run;   // fill cursor
            run += local[j];
        }
    }
}

__global__ void __launch_bounds__(256)
fill_kernel(const float* __restrict__ ew, int E, int Nn)
{
    int i = blockIdx.x * blockDim.x + threadIdx.x;
    if (i >= E) return;
    int s = g_ei[i];
    int d = g_ei[E + i];
    if ((unsigned)s >= (unsigned)Nn || (unsigned)d >= (unsigned)Nn) return;
    int p = atomicAdd(&g_deg[d], 1);
    g_src[p] = s;
    g_wp[p]  = ew[i];
}

// ---------------------------------------------------------------------------
// Dual-output SGEMM with packed f32x2 FMA.
//   Z[m,:] = act(A[m,:]) @ Wrel ;  H[m,:] = act(A[m,:]) @ Wroot + bias
// Block tile 128x64, BK=16, 256 threads, thread tile 8 rows x 4 cols.
// grid = (ceil(M/128), 4); blockIdx.y>=2 -> root half (cols 128..255).
// ---------------------------------------------------------------------------
template<bool RELU>
__global__ void __launch_bounds__(256)
gemm_dual(const float* __restrict__ A,
          const float* __restrict__ Wrel,
          const float* __restrict__ Wroot,
          const float* __restrict__ bias,
          float* __restrict__ Z,
          float* __restrict__ H,
          int M)
{
    const int BM = 128, BN = 64, BK = 16;
    __shared__ __align__(16) float As[BK][BM];
    __shared__ __align__(16) u64   Bs[BK][BN];   // duplicated pairs

    const int tid = threadIdx.x;
    const int tx  = tid & 15;            // col group: 4 cols
    const int ty  = tid >> 4;            // row group: 8 rows
    const int row0 = blockIdx.x * BM;
    const int col0 = blockIdx.y * BN;    // 0,64,128,192

    u64 acc[4][4];
    #pragma unroll
    for (int i = 0; i < 4; i++)
        #pragma unroll
        for (int j = 0; j < 4; j++) acc[i][j] = 0ull;

    for (int k0 = 0; k0 < 128; k0 += BK) {
        #pragma unroll
        for (int i = tid; i < 512; i += 256) {
            int r  = i >> 2;
            int kq = i & 3;
            int gr = row0 + r;
            float4 a = make_float4(0.f, 0.f, 0.f, 0.f);
            if (gr < M) a = *(const float4*)(A + (size_t)gr * 128 + k0 + kq * 4);
            if (RELU) {
                a.x = fmaxf(a.x, 0.f); a.y = fmaxf(a.y, 0.f);
                a.z = fmaxf(a.z, 0.f); a.w = fmaxf(a.w, 0.f);
            }
            As[kq * 4 + 0][r] = a.x;
            As[kq * 4 + 1][r] = a.y;
            As[kq * 4 + 2][r] = a.z;
            As[kq * 4 + 3][r] = a.w;
        }
        #pragma unroll
        for (int i = tid; i < BK * BN; i += 256) {
            int k  = i >> 6;
            int n  = i & 63;
            int gn = col0 + n;
            float b = (gn < 128) ? Wrel [(k0 + k) * 128 + gn]
                                 : Wroot[(k0 + k) * 128 + gn - 128];
            Bs[k][n] = pack_dup(b);
        }
        __syncthreads();

        #pragma unroll
        for (int k = 0; k < BK; k++) {
            const ulonglong2* ap = (const ulonglong2*)&As[k][ty * 8];
            ulonglong2 a01 = ap[0];
            ulonglong2 a23 = ap[1];
            const ulonglong2* bp = (const ulonglong2*)&Bs[k][tx * 4];
            ulonglong2 b01 = bp[0];
            ulonglong2 b23 = bp[1];
            u64 av[4] = {a01.x, a01.y, a23.x, a23.y};
            u64 bv[4] = {b01.x, b01.y, b23.x, b23.y};
            #pragma unroll
            for (int i = 0; i < 4; i++)
                #pragma unroll
                for (int j = 0; j < 4; j++)
                    acc[i][j] = fma2(av[i], bv[j], acc[i][j]);
        }
        __syncthreads();
    }

    const int gn0 = col0 + tx * 4;
    const bool relHalf = (gn0 < 128);
    float4 bv4 = make_float4(0.f, 0.f, 0.f, 0.f);
    if (!relHalf) bv4 = *(const float4*)(bias + gn0 - 128);

    #pragma unroll
    for (int rp = 0; rp < 4; rp++) {
        float2 f0 = unpack2(acc[rp][0]);
        float2 f1 = unpack2(acc[rp][1]);
        float2 f2 = unpack2(acc[rp][2]);
        float2 f3 = unpack2(acc[rp][3]);
        int r0 = row0 + ty * 8 + rp * 2;
        int r1 = r0 + 1;
        if (relHalf) {
            if (r0 < M) *(float4*)(Z + (size_t)r0 * 128 + gn0) =
                make_float4(f0.x, f1.x, f2.x, f3.x);
            if (r1 < M) *(float4*)(Z + (size_t)r1 * 128 + gn0) =
                make_float4(f0.y, f1.y, f2.y, f3.y);
        } else {
            int c0 = gn0 - 128;
            if (r0 < M) *(float4*)(H + (size_t)r0 * 128 + c0) =
                make_float4(f0.x + bv4.x, f1.x + bv4.y, f2.x + bv4.z, f3.x + bv4.w);
            if (r1 < M) *(float4*)(H + (size_t)r1 * 128 + c0) =
                make_float4(f0.y + bv4.x, f1.y + bv4.y, f2.y + bv4.z, f3.y + bv4.w);
        }
    }
}

// ---------------------------------------------------------------------------
// CSR gather: one warp per dst node.  Lane owns float4 of the 128-wide row.
// Accumulate all incoming edges in registers, single RMW of H (no atomics).
// 4-way unroll for memory-level parallelism (mean degree ~12.8).
// ---------------------------------------------------------------------------
__global__ void __launch_bounds__(256)
gather_kernel(const float* __restrict__ Z,
              float* __restrict__ H,
              int Nn)
{
    int warp = (int)((blockIdx.x * (unsigned)blockDim.x + threadIdx.x) >> 5);
    int lane = threadIdx.x & 31;
    if (warp >= Nn) return;

    int lo = g_off[warp];
    int hi = g_off[warp + 1];
    if (lo == hi) return;

    float4 acc = make_float4(0.f, 0.f, 0.f, 0.f);
    int e = lo;
    for (; e + 3 < hi; e += 4) {
        int   s0 = g_src[e],   s1 = g_src[e+1], s2 = g_src[e+2], s3 = g_src[e+3];
        float w0 = g_wp[e],    w1 = g_wp[e+1],  w2 = g_wp[e+2],  w3 = g_wp[e+3];
        float4 v0 = ((const float4*)(Z + (size_t)s0 * 128))[lane];
        float4 v1 = ((const float4*)(Z + (size_t)s1 * 128))[lane];
        float4 v2 = ((const float4*)(Z + (size_t)s2 * 128))[lane];
        float4 v3 = ((const float4*)(Z + (size_t)s3 * 128))[lane];
        acc.x = fmaf(w0, v0.x, acc.x); acc.y = fmaf(w0, v0.y, acc.y);
        acc.z = fmaf(w0, v0.z, acc.z); acc.w = fmaf(w0, v0.w, acc.w);
        acc.x = fmaf(w1, v1.x, acc.x); acc.y = fmaf(w1, v1.y, acc.y);
        acc.z = fmaf(w1, v1.z, acc.z); acc.w = fmaf(w1, v1.w, acc.w);
        acc.x = fmaf(w2, v2.x, acc.x); acc.y = fmaf(w2, v2.y, acc.y);
        acc.z = fmaf(w2, v2.z, acc.z); acc.w = fmaf(w2, v2.w, acc.w);
        acc.x = fmaf(w3, v3.x, acc.x); acc.y = fmaf(w3, v3.y, acc.y);
        acc.z = fmaf(w3, v3.z, acc.z); acc.w = fmaf(w3, v3.w, acc.w);
    }
    for (; e < hi; e++) {
        int   s0 = g_src[e];
        float w0 = g_wp[e];
        float4 v0 = ((const float4*)(Z + (size_t)s0 * 128))[lane];
        acc.x = fmaf(w0, v0.x, acc.x); acc.y = fmaf(w0, v0.y, acc.y);
        acc.z = fmaf(w0, v0.z, acc.z); acc.w = fmaf(w0, v0.w, acc.w);
    }

    float4* hp = ((float4*)(H + (size_t)warp * 128)) + lane;
    float4 h = *hp;
    h.x += acc.x; h.y += acc.y; h.z += acc.z; h.w += acc.w;
    *hp = h;
}

// ---------------------------------------------------------------------------
// Pool: one block per graph (batch sorted -> binary search range).
// Per-feature max of relu(H2), dot with W_lin, +b, sigmoid.
// Also re-zeroes g_deg for the next call (first call: static zero-init).
// ---------------------------------------------------------------------------
__global__ void __launch_bounds__(128)
pool_kernel(const float* __restrict__ H2,
            const float* __restrict__ Wlin,
            const float* __restrict__ blin,
            float* __restrict__ out,
            int Nn)
{
    int g = blockIdx.x;
    int t = threadIdx.x;

    // zero degree histogram for next call (grid-stride)
    for (int i = g * 128 + t; i < Nn; i += gridDim.x * 128)
        g_deg[i] = 0;

    __shared__ int s_range[2];
    if (t < 2) {
        int target = g + t;
        int lo = 0, hi = Nn;
        while (lo < hi) {
            int mid = (lo + hi) >> 1;
            if (g_batch[mid] < target) lo = mid + 1; else hi = mid;
        }
        s_range[t] = lo;
    }
    __syncthreads();
    int lo = s_range[0], hi = s_range[1];

    float m = -INFINITY;
    for (int n = lo; n < hi; n++)
        m = fmaxf(m, H2[(size_t)n * 128 + t]);
    if (hi > lo) m = fmaxf(m, 0.0f);   // relu-before-max == clamp of max

    float v = m * Wlin[t];

    __shared__ float red[128];
    red[t] = v;
    __syncthreads();
    #pragma unroll
    for (int s = 64; s > 0; s >>= 1) {
        if (t < s) red[t] += red[t + s];
        __syncthreads();
    }
    if (t == 0) {
        float logit = red[0] + blin[0];
        out[g] = 1.0f / (1.0f + expf(-logit));
    }
}

// ---------------------------------------------------------------------------
extern "C" void kernel_launch(void* const* d_in, const int* in_sizes, int n_in,
                              void* d_out, int out_size)
{
    const float* x      = (const float*) d_in[0];
    const int*   ei     = (const int*)   d_in[1];
    const int*   batch  = (const int*)   d_in[2];
    const float* ew     = (const float*) d_in[3];
    const float* W1rel  = (const float*) d_in[4];
    const float* b1     = (const float*) d_in[5];
    const float* W1root = (const float*) d_in[6];
    const float* W2rel  = (const float*) d_in[7];
    const float* b2     = (const float*) d_in[8];
    const float* W2root = (const float*) d_in[9];
    const float* Wlin   = (const float*) d_in[10];
    const float* blin   = (const float*) d_in[11];
    float* out = (float*)d_out;

    int M = in_sizes[0] / 128;   // nodes
    int E = in_sizes[1] / 2;     // edges
    int G = out_size;            // graphs
    if (M > MAX_NODES) M = MAX_NODES;
    if (E > MAX_EDGES) E = MAX_EDGES;

    float *Z, *H1, *H2;
    cudaGetSymbolAddress((void**)&Z,  g_Z);
    cudaGetSymbolAddress((void**)&H1, g_H1);
    cudaGetSymbolAddress((void**)&H2, g_H2);

    int NB = (M + SCAN_CHUNK - 1) / SCAN_CHUNK;

    // 1: convert + detect + histogram   (g_deg zeroed by prior pool / load-init)
    {
        int work = 2 * E;
        if (M > work) work = M;
        convert_hist<<<(work + 255) / 256, 256>>>(ei, batch, E, M);
    }
    // 2-4: blocked exclusive scan of degrees
    partial_kernel  <<<NB, 256>>>(M);
    scan_part_kernel<<<1, 64>>>(NB, M);
    writeoff_kernel <<<NB, 256>>>(M);
    // 5: CSR fill
    fill_kernel<<<(E + 255) / 256, 256>>>(ew, E, M);

    dim3 ggrid((M + 127) / 128, 4);
    int gatherBlocks = (M * 32 + 255) / 256;

    // 6: Layer 1 GEMM   (profiled launch)
    gemm_dual<false><<<ggrid, 256>>>(x, W1rel, W1root, b1, Z, H1, M);
    gather_kernel<<<gatherBlocks, 256>>>(Z, H1, M);
    // Layer 2
    gemm_dual<true><<<ggrid, 256>>>(H1, W2rel, W2root, b2, Z, H2, M);
    gather_kernel<<<gatherBlocks, 256>>>(Z, H2, M);
    // Pool + linear + sigmoid (+ deg re-zero for next call)
    pool_kernel<<<G, 128>>>(H2, Wlin, blin, out, M);
}

// round 7
// speedup vs baseline: 1.6697x; 1.3003x over previous
#include <cuda_runtime.h>
#include <math.h>

// ---------------------------------------------------------------------------
// simpleGNN: 2x GraphConv(128->128) + ReLU, segment_max pool, Linear(128->1),
// sigmoid.
// GEMM-first reordering; CSR gather (no float atomics); parallel CSR build.
// R7: GEMM moved to tensor cores: mma.sync.m16n8k8.tf32 with 3-term split-TF32
//     (hi*hi + hi*lo + lo*hi) for fp32-grade accuracy.
// ---------------------------------------------------------------------------

#define MAX_NODES 50000
#define MAX_EDGES 640000
#define FDIM      128
#define SCAN_CHUNK 1024
#define MAX_PARTS  64

typedef unsigned int u32;

__device__ float g_Z    [MAX_NODES * FDIM];
__device__ float g_H1   [MAX_NODES * FDIM];
__device__ float g_H2   [MAX_NODES * FDIM];
__device__ int   g_ei   [2 * MAX_EDGES];
__device__ int   g_batch[MAX_NODES];
__device__ int   g_deg  [MAX_NODES];
__device__ int   g_off  [MAX_NODES + 1];
__device__ int   g_part [MAX_PARTS];
__device__ int   g_src  [MAX_EDGES];
__device__ float g_wp   [MAX_EDGES];

// ---------------- tf32 helpers ---------------------------------------------
__device__ __forceinline__ u32 f2tf32(float f) {
    u32 u;
    asm("cvt.rna.tf32.f32 %0, %1;" : "=r"(u) : "f"(f));
    return u;
}
__device__ __forceinline__ void mma_tf32(float c[4], const u32 a[4], const u32 b[2]) {
    asm volatile(
        "mma.sync.aligned.m16n8k8.row.col.f32.tf32.tf32.f32 "
        "{%0,%1,%2,%3}, {%4,%5,%6,%7}, {%8,%9}, {%0,%1,%2,%3};"
        : "+f"(c[0]), "+f"(c[1]), "+f"(c[2]), "+f"(c[3])
        : "r"(a[0]), "r"(a[1]), "r"(a[2]), "r"(a[3]), "r"(b[0]), "r"(b[1]));
}

// ---------------------------------------------------------------------------
// convert + histogram + dtype detect (fused).
// ---------------------------------------------------------------------------
__global__ void __launch_bounds__(256)
convert_hist(const int* __restrict__ ei,
             const int* __restrict__ batch,
             int E, int Nn)
{
    __shared__ int s_is64;
    if (threadIdx.x == 0) {
        int any = 0;
        #pragma unroll
        for (int k = 1; k < 128; k += 2) any |= ei[k];
        s_is64 = (any == 0);
    }
    __syncthreads();
    int f = s_is64;

    int i = blockIdx.x * blockDim.x + threadIdx.x;
    int twoE = 2 * E;
    if (i < twoE) {
        int v = f ? ei[2 * i] : ei[i];
        g_ei[i] = v;
        if (i >= E && (unsigned)v < (unsigned)Nn)
            atomicAdd(&g_deg[v], 1);
    }
    if (i < Nn)
        g_batch[i] = f ? batch[2 * i] : batch[i];
}

// ---------------------------------------------------------------------------
// Blocked exclusive scan of g_deg -> g_off.
// ---------------------------------------------------------------------------
__global__ void __launch_bounds__(256)
partial_kernel(int Nn)
{
    __shared__ int red[256];
    int t = threadIdx.x;
    int base = blockIdx.x * SCAN_CHUNK + t * 4;
    int s = 0;
    #pragma unroll
    for (int j = 0; j < 4; j++) {
        int idx = base + j;
        s += (idx < Nn) ? g_deg[idx] : 0;
    }
    red[t] = s;
    __syncthreads();
    #pragma unroll
    for (int d = 128; d > 0; d >>= 1) {
        if (t < d) red[t] += red[t + d];
        __syncthreads();
    }
    if (t == 0) g_part[blockIdx.x] = red[0];
}

__global__ void __launch_bounds__(64)
scan_part_kernel(int NB, int Nn)
{
    __shared__ int s[MAX_PARTS];
    int t = threadIdx.x;
    s[t] = (t < NB) ? g_part[t] : 0;
    __syncthreads();
    #pragma unroll
    for (int d = 1; d < MAX_PARTS; d <<= 1) {
        int v = (t >= d) ? s[t - d] : 0;
        __syncthreads();
        s[t] += v;
        __syncthreads();
    }
    if (t < NB) g_part[t] = (t == 0) ? 0 : s[t - 1];
    if (t == MAX_PARTS - 1) g_off[Nn] = s[MAX_PARTS - 1];
}

__global__ void __launch_bounds__(256)
writeoff_kernel(int Nn)
{
    __shared__ int sums[256];
    int t = threadIdx.x;
    int base = blockIdx.x * SCAN_CHUNK + t * 4;

    int local[4];
    int s = 0;
    #pragma unroll
    for (int j = 0; j < 4; j++) {
        int idx = base + j;
        local[j] = (idx < Nn) ? g_deg[idx] : 0;
        s += local[j];
    }
    sums[t] = s;
    __syncthreads();
    #pragma unroll
    for (int d = 1; d < 256; d <<= 1) {
        int v = (t >= d) ? sums[t - d] : 0;
        __syncthreads();
        sums[t] += v;
        __syncthreads();
    }
    int run = g_part[blockIdx.x] + ((t == 0) ? 0 : sums[t - 1]);
    #pragma unroll
    for (int j = 0; j < 4; j++) {
        int idx = base + j;
        if (idx < Nn) {
            g_off[idx] = run;
            g_deg[idx] = run;
            run += local[j];
        }
    }
}

__global__ void __launch_bounds__(256)
fill_kernel(const float* __restrict__ ew, int E, int Nn)
{
    int i = blockIdx.x * blockDim.x + threadIdx.x;
    if (i >= E) return;
    int s = g_ei[i];
    int d = g_ei[E + i];
    if ((unsigned)s >= (unsigned)Nn || (unsigned)d >= (unsigned)Nn) return;
    int p = atomicAdd(&g_deg[d], 1);
    g_src[p] = s;
    g_wp[p]  = ew[i];
}

// ---------------------------------------------------------------------------
// Dual-output GEMM on tensor cores (split-TF32, 3 mma terms).
//   Z[m,:] = act(A[m,:]) @ Wrel ;  H[m,:] = act(A[m,:]) @ Wroot + bias
// Block tile 128x64, BK=16, 256 threads (8 warps: 4m x 2n, warp tile 32x32).
// A smem [m][20] (stride 20 -> conflict-free frag loads), B smem [k][68].
// grid = (ceil(M/128), 4); blockIdx.y>=2 -> root half (cols 128..255).
// ---------------------------------------------------------------------------
template<bool RELU>
__global__ void __launch_bounds__(256)
gemm_dual(const float* __restrict__ A,
          const float* __restrict__ Wrel,
          const float* __restrict__ Wroot,
          const float* __restrict__ bias,
          float* __restrict__ Z,
          float* __restrict__ H,
          int M)
{
    const int ASTR = 20, BSTR = 68;
    __shared__ u32 Ah[128 * ASTR];
    __shared__ u32 Al[128 * ASTR];
    __shared__ u32 Bh[16 * BSTR];
    __shared__ u32 Bl[16 * BSTR];

    const int tid   = threadIdx.x;
    const int wid   = tid >> 5;
    const int lane  = tid & 31;
    const int grp   = lane >> 2;      // 0..7
    const int tig   = lane & 3;       // 0..3
    const int warpM = wid >> 1;       // 0..3
    const int warpN = wid & 1;        // 0..1
    const int row0  = blockIdx.x * 128;
    const int col0  = blockIdx.y * 64;   // 0,64,128,192

    float acc[2][4][4];
    #pragma unroll
    for (int mt = 0; mt < 2; mt++)
        #pragma unroll
        for (int nt = 0; nt < 4; nt++)
            #pragma unroll
            for (int c = 0; c < 4; c++) acc[mt][nt][c] = 0.f;

    for (int k0 = 0; k0 < 128; k0 += 16) {
        // ---- load A tile: 128 rows x 16 k  (512 float4, 2 per thread) ----
        #pragma unroll
        for (int j = 0; j < 2; j++) {
            int idx = tid + j * 256;          // 0..511
            int r   = idx >> 2;               // 0..127
            int kq  = idx & 3;                // float4 within row
            int gr  = row0 + r;
            float4 a = make_float4(0.f, 0.f, 0.f, 0.f);
            if (gr < M) a = *(const float4*)(A + (size_t)gr * 128 + k0 + kq * 4);
            if (RELU) {
                a.x = fmaxf(a.x, 0.f); a.y = fmaxf(a.y, 0.f);
                a.z = fmaxf(a.z, 0.f); a.w = fmaxf(a.w, 0.f);
            }
            float av[4] = {a.x, a.y, a.z, a.w};
            #pragma unroll
            for (int c = 0; c < 4; c++) {
                u32 hb = f2tf32(av[c]);
                float hf = __uint_as_float(hb);
                u32 lb = f2tf32(av[c] - hf);
                Ah[r * ASTR + kq * 4 + c] = hb;
                Al[r * ASTR + kq * 4 + c] = lb;
            }
        }
        // ---- load B tile: 16 k x 64 n  (256 float4, 1 per thread) ----
        {
            int kr = tid >> 4;                // 0..15
            int nq = tid & 15;                // float4 within row
            int gn = col0 + nq * 4;
            float4 b = (gn < 128)
                ? *(const float4*)(Wrel  + (size_t)(k0 + kr) * 128 + gn)
                : *(const float4*)(Wroot + (size_t)(k0 + kr) * 128 + gn - 128);
            float bv[4] = {b.x, b.y, b.z, b.w};
            #pragma unroll
            for (int c = 0; c < 4; c++) {
                u32 hb = f2tf32(bv[c]);
                float hf = __uint_as_float(hb);
                u32 lb = f2tf32(bv[c] - hf);
                Bh[kr * BSTR + nq * 4 + c] = hb;
                Bl[kr * BSTR + nq * 4 + c] = lb;
            }
        }
        __syncthreads();

        // ---- 2 k-steps of 8 ----
        #pragma unroll
        for (int ks = 0; ks < 2; ks++) {
            const int k = ks * 8;
            u32 ah[2][4], al[2][4], bh[4][2], bl[4][2];
            #pragma unroll
            for (int mt = 0; mt < 2; mt++) {
                int m = warpM * 32 + mt * 16 + grp;
                int b0 = m * ASTR + k + tig;
                ah[mt][0] = Ah[b0];
                ah[mt][1] = Ah[b0 + 8 * ASTR];
                ah[mt][2] = Ah[b0 + 4];
                ah[mt][3] = Ah[b0 + 8 * ASTR + 4];
                al[mt][0] = Al[b0];
                al[mt][1] = Al[b0 + 8 * ASTR];
                al[mt][2] = Al[b0 + 4];
                al[mt][3] = Al[b0 + 8 * ASTR + 4];
            }
            #pragma unroll
            for (int nt = 0; nt < 4; nt++) {
                int n  = warpN * 32 + nt * 8 + grp;
                int b0 = (k + tig) * BSTR + n;
                bh[nt][0] = Bh[b0];
                bh[nt][1] = Bh[b0 + 4 * BSTR];
                bl[nt][0] = Bl[b0];
                bl[nt][1] = Bl[b0 + 4 * BSTR];
            }
            #pragma unroll
            for (int mt = 0; mt < 2; mt++)
                #pragma unroll
                for (int nt = 0; nt < 4; nt++) {
                    mma_tf32(acc[mt][nt], ah[mt], bh[nt]);   // hi*hi
                    mma_tf32(acc[mt][nt], ah[mt], bl[nt]);   // hi*lo
                    mma_tf32(acc[mt][nt], al[mt], bh[nt]);   // lo*hi
                }
        }
        __syncthreads();
    }

    // ---- epilogue: float2 stores, Z or H+bias ----
    const bool relHalf = (col0 < 128);
    #pragma unroll
    for (int mt = 0; mt < 2; mt++) {
        int r0 = row0 + warpM * 32 + mt * 16 + grp;
        int r1 = r0 + 8;
        #pragma unroll
        for (int nt = 0; nt < 4; nt++) {
            int cb = col0 + warpN * 32 + nt * 8 + 2 * tig;
            if (relHalf) {
                if (r0 < M) *(float2*)(Z + (size_t)r0 * 128 + cb) =
                    make_float2(acc[mt][nt][0], acc[mt][nt][1]);
                if (r1 < M) *(float2*)(Z + (size_t)r1 * 128 + cb) =
                    make_float2(acc[mt][nt][2], acc[mt][nt][3]);
            } else {
                int c = cb - 128;
                float bx = bias[c], by = bias[c + 1];
                if (r0 < M) *(float2*)(H + (size_t)r0 * 128 + c) =
                    make_float2(acc[mt][nt][0] + bx, acc[mt][nt][1] + by);
                if (r1 < M) *(float2*)(H + (size_t)r1 * 128 + c) =
                    make_float2(acc[mt][nt][2] + bx, acc[mt][nt][3] + by);
            }
        }
    }
}

// ---------------------------------------------------------------------------
// CSR gather: one warp per dst node, 4-way unrolled, no atomics.
// ---------------------------------------------------------------------------
__global__ void __launch_bounds__(256)
gather_kernel(const float* __restrict__ Z,
              float* __restrict__ H,
              int Nn)
{
    int warp = (int)((blockIdx.x * (unsigned)blockDim.x + threadIdx.x) >> 5);
    int lane = threadIdx.x & 31;
    if (warp >= Nn) return;

    int lo = g_off[warp];
    int hi = g_off[warp + 1];
    if (lo == hi) return;

    float4 acc = make_float4(0.f, 0.f, 0.f, 0.f);
    int e = lo;
    for (; e + 3 < hi; e += 4) {
        int   s0 = g_src[e],   s1 = g_src[e+1], s2 = g_src[e+2], s3 = g_src[e+3];
        float w0 = g_wp[e],    w1 = g_wp[e+1],  w2 = g_wp[e+2],  w3 = g_wp[e+3];
        float4 v0 = ((const float4*)(Z + (size_t)s0 * 128))[lane];
        float4 v1 = ((const float4*)(Z + (size_t)s1 * 128))[lane];
        float4 v2 = ((const float4*)(Z + (size_t)s2 * 128))[lane];
        float4 v3 = ((const float4*)(Z + (size_t)s3 * 128))[lane];
        acc.x = fmaf(w0, v0.x, acc.x); acc.y = fmaf(w0, v0.y, acc.y);
        acc.z = fmaf(w0, v0.z, acc.z); acc.w = fmaf(w0, v0.w, acc.w);
        acc.x = fmaf(w1, v1.x, acc.x); acc.y = fmaf(w1, v1.y, acc.y);
        acc.z = fmaf(w1, v1.z, acc.z); acc.w = fmaf(w1, v1.w, acc.w);
        acc.x = fmaf(w2, v2.x, acc.x); acc.y = fmaf(w2, v2.y, acc.y);
        acc.z = fmaf(w2, v2.z, acc.z); acc.w = fmaf(w2, v2.w, acc.w);
        acc.x = fmaf(w3, v3.x, acc.x); acc.y = fmaf(w3, v3.y, acc.y);
        acc.z = fmaf(w3, v3.z, acc.z); acc.w = fmaf(w3, v3.w, acc.w);
    }
    for (; e < hi; e++) {
        int   s0 = g_src[e];
        float w0 = g_wp[e];
        float4 v0 = ((const float4*)(Z + (size_t)s0 * 128))[lane];
        acc.x = fmaf(w0, v0.x, acc.x); acc.y = fmaf(w0, v0.y, acc.y);
        acc.z = fmaf(w0, v0.z, acc.z); acc.w = fmaf(w0, v0.w, acc.w);
    }

    float4* hp = ((float4*)(H + (size_t)warp * 128)) + lane;
    float4 h = *hp;
    h.x += acc.x; h.y += acc.y; h.z += acc.z; h.w += acc.w;
    *hp = h;
}

// ---------------------------------------------------------------------------
// Pool + linear + sigmoid; re-zeroes g_deg for the next call.
// ---------------------------------------------------------------------------
__global__ void __launch_bounds__(128)
pool_kernel(const float* __restrict__ H2,
            const float* __restrict__ Wlin,
            const float* __restrict__ blin,
            float* __restrict__ out,
            int Nn)
{
    int g = blockIdx.x;
    int t = threadIdx.x;

    for (int i = g * 128 + t; i < Nn; i += gridDim.x * 128)
        g_deg[i] = 0;

    __shared__ int s_range[2];
    if (t < 2) {
        int target = g + t;
        int lo = 0, hi = Nn;
        while (lo < hi) {
            int mid = (lo + hi) >> 1;
            if (g_batch[mid] < target) lo = mid + 1; else hi = mid;
        }
        s_range[t] = lo;
    }
    __syncthreads();
    int lo = s_range[0], hi = s_range[1];

    float m = -INFINITY;
    for (int n = lo; n < hi; n++)
        m = fmaxf(m, H2[(size_t)n * 128 + t]);
    if (hi > lo) m = fmaxf(m, 0.0f);

    float v = m * Wlin[t];

    __shared__ float red[128];
    red[t] = v;
    __syncthreads();
    #pragma unroll
    for (int s = 64; s > 0; s >>= 1) {
        if (t < s) red[t] += red[t + s];
        __syncthreads();
    }
    if (t == 0) {
        float logit = red[0] + blin[0];
        out[g] = 1.0f / (1.0f + expf(-logit));
    }
}

// ---------------------------------------------------------------------------
extern "C" void kernel_launch(void* const* d_in, const int* in_sizes, int n_in,
                              void* d_out, int out_size)
{
    const float* x      = (const float*) d_in[0];
    const int*   ei     = (const int*)   d_in[1];
    const int*   batch  = (const int*)   d_in[2];
    const float* ew     = (const float*) d_in[3];
    const float* W1rel  = (const float*) d_in[4];
    const float* b1     = (const float*) d_in[5];
    const float* W1root = (const float*) d_in[6];
    const float* W2rel  = (const float*) d_in[7];
    const float* b2     = (const float*) d_in[8];
    const float* W2root = (const float*) d_in[9];
    const float* Wlin   = (const float*) d_in[10];
    const float* blin   = (const float*) d_in[11];
    float* out = (float*)d_out;

    int M = in_sizes[0] / 128;
    int E = in_sizes[1] / 2;
    int G = out_size;
    if (M > MAX_NODES) M = MAX_NODES;
    if (E > MAX_EDGES) E = MAX_EDGES;

    float *Z, *H1, *H2;
    cudaGetSymbolAddress((void**)&Z,  g_Z);
    cudaGetSymbolAddress((void**)&H1, g_H1);
    cudaGetSymbolAddress((void**)&H2, g_H2);

    int NB = (M + SCAN_CHUNK - 1) / SCAN_CHUNK;

    {
        int work = 2 * E;
        if (M > work) work = M;
        convert_hist<<<(work + 255) / 256, 256>>>(ei, batch, E, M);
    }
    partial_kernel  <<<NB, 256>>>(M);
    scan_part_kernel<<<1, 64>>>(NB, M);
    writeoff_kernel <<<NB, 256>>>(M);
    fill_kernel<<<(E + 255) / 256, 256>>>(ew, E, M);

    dim3 ggrid((M + 127) / 128, 4);
    int gatherBlocks = (M * 32 + 255) / 256;

    gemm_dual<false><<<ggrid, 256>>>(x, W1rel, W1root, b1, Z, H1, M);
    gather_kernel<<<gatherBlocks, 256>>>(Z, H1, M);
    gemm_dual<true><<<ggrid, 256>>>(H1, W2rel, W2root, b2, Z, H2, M);
    gather_kernel<<<gatherBlocks, 256>>>(Z, H2, M);
    pool_kernel<<<G, 128>>>(H2, Wlin, blin, out, M);
}

// round 8
// speedup vs baseline: 1.7680x; 1.0589x over previous
#include <cuda_runtime.h>
#include <math.h>

// ---------------------------------------------------------------------------
// simpleGNN: 2x GraphConv(128->128) + ReLU, segment_max pool, Linear(128->1),
// sigmoid.
// GEMM-first reordering; CSR gather (no float atomics); parallel CSR build.
// R8: BN=128 tensor GEMM (halved A traffic + conversions, conflict-free B
//     stride 133), launch order puts gemm1 at slot 4 (ncu captures it),
//     8-way unrolled gather.
// ---------------------------------------------------------------------------

#define MAX_NODES 50000
#define MAX_EDGES 640000
#define FDIM      128
#define SCAN_CHUNK 1024
#define MAX_PARTS  64

typedef unsigned int u32;

__device__ float g_Z    [MAX_NODES * FDIM];
__device__ float g_H1   [MAX_NODES * FDIM];
__device__ float g_H2   [MAX_NODES * FDIM];
__device__ int   g_ei   [2 * MAX_EDGES];
__device__ int   g_batch[MAX_NODES];
__device__ int   g_deg  [MAX_NODES];
__device__ int   g_off  [MAX_NODES + 1];
__device__ int   g_part [MAX_PARTS];
__device__ int   g_src  [MAX_EDGES];
__device__ float g_wp   [MAX_EDGES];

// ---------------- tf32 helpers ---------------------------------------------
__device__ __forceinline__ u32 f2tf32(float f) {
    u32 u;
    asm("cvt.rna.tf32.f32 %0, %1;" : "=r"(u) : "f"(f));
    return u;
}
__device__ __forceinline__ void mma_tf32(float c[4], const u32 a[4], const u32 b[2]) {
    asm volatile(
        "mma.sync.aligned.m16n8k8.row.col.f32.tf32.tf32.f32 "
        "{%0,%1,%2,%3}, {%4,%5,%6,%7}, {%8,%9}, {%0,%1,%2,%3};"
        : "+f"(c[0]), "+f"(c[1]), "+f"(c[2]), "+f"(c[3])
        : "r"(a[0]), "r"(a[1]), "r"(a[2]), "r"(a[3]), "r"(b[0]), "r"(b[1]));
}

// ---------------------------------------------------------------------------
// convert + histogram + dtype detect (fused).
// ---------------------------------------------------------------------------
__global__ void __launch_bounds__(256)
convert_hist(const int* __restrict__ ei,
             const int* __restrict__ batch,
             int E, int Nn)
{
    __shared__ int s_is64;
    if (threadIdx.x == 0) {
        int any = 0;
        #pragma unroll
        for (int k = 1; k < 128; k += 2) any |= ei[k];
        s_is64 = (any == 0);
    }
    __syncthreads();
    int f = s_is64;

    int i = blockIdx.x * blockDim.x + threadIdx.x;
    int twoE = 2 * E;
    if (i < twoE) {
        int v = f ? ei[2 * i] : ei[i];
        g_ei[i] = v;
        if (i >= E && (unsigned)v < (unsigned)Nn)
            atomicAdd(&g_deg[v], 1);
    }
    if (i < Nn)
        g_batch[i] = f ? batch[2 * i] : batch[i];
}

// ---------------------------------------------------------------------------
// Blocked exclusive scan of g_deg -> g_off.
// ---------------------------------------------------------------------------
__global__ void __launch_bounds__(256)
partial_kernel(int Nn)
{
    __shared__ int red[256];
    int t = threadIdx.x;
    int base = blockIdx.x * SCAN_CHUNK + t * 4;
    int s = 0;
    #pragma unroll
    for (int j = 0; j < 4; j++) {
        int idx = base + j;
        s += (idx < Nn) ? g_deg[idx] : 0;
    }
    red[t] = s;
    __syncthreads();
    #pragma unroll
    for (int d = 128; d > 0; d >>= 1) {
        if (t < d) red[t] += red[t + d];
        __syncthreads();
    }
    if (t == 0) g_part[blockIdx.x] = red[0];
}

__global__ void __launch_bounds__(64)
scan_part_kernel(int NB, int Nn)
{
    __shared__ int s[MAX_PARTS];
    int t = threadIdx.x;
    s[t] = (t < NB) ? g_part[t] : 0;
    __syncthreads();
    #pragma unroll
    for (int d = 1; d < MAX_PARTS; d <<= 1) {
        int v = (t >= d) ? s[t - d] : 0;
        __syncthreads();
        s[t] += v;
        __syncthreads();
    }
    if (t < NB) g_part[t] = (t == 0) ? 0 : s[t - 1];
    if (t == MAX_PARTS - 1) g_off[Nn] = s[MAX_PARTS - 1];
}

__global__ void __launch_bounds__(256)
writeoff_kernel(int Nn)
{
    __shared__ int sums[256];
    int t = threadIdx.x;
    int base = blockIdx.x * SCAN_CHUNK + t * 4;

    int local[4];
    int s = 0;
    #pragma unroll
    for (int j = 0; j < 4; j++) {
        int idx = base + j;
        local[j] = (idx < Nn) ? g_deg[idx] : 0;
        s += local[j];
    }
    sums[t] = s;
    __syncthreads();
    #pragma unroll
    for (int d = 1; d < 256; d <<= 1) {
        int v = (t >= d) ? sums[t - d] : 0;
        __syncthreads();
        sums[t] += v;
        __syncthreads();
    }
    int run = g_part[blockIdx.x] + ((t == 0) ? 0 : sums[t - 1]);
    #pragma unroll
    for (int j = 0; j < 4; j++) {
        int idx = base + j;
        if (idx < Nn) {
            g_off[idx] = run;
            g_deg[idx] = run;
            run += local[j];
        }
    }
}

__global__ void __launch_bounds__(256)
fill_kernel(const float* __restrict__ ew, int E, int Nn)
{
    int i = blockIdx.x * blockDim.x + threadIdx.x;
    if (i >= E) return;
    int s = g_ei[i];
    int d = g_ei[E + i];
    if ((unsigned)s >= (unsigned)Nn || (unsigned)d >= (unsigned)Nn) return;
    int p = atomicAdd(&g_deg[d], 1);
    g_src[p] = s;
    g_wp[p]  = ew[i];
}

// ---------------------------------------------------------------------------
// Dual-output GEMM on tensor cores (split-TF32, 3 mma terms).
//   y==0: Z[m,:] = act(A[m,:]) @ Wrel       (cols 0..127)
//   y==1: H[m,:] = act(A[m,:]) @ Wroot + b  (cols 128..255)
// Block tile 128x128, BK=16, 256 threads (8 warps: 4m x 2n, warp tile 32x64).
// A smem stride 20, B smem stride 133 (both conflict-free for frag loads).
// ---------------------------------------------------------------------------
template<bool RELU>
__global__ void __launch_bounds__(256)
gemm_dual(const float* __restrict__ A,
          const float* __restrict__ Wrel,
          const float* __restrict__ Wroot,
          const float* __restrict__ bias,
          float* __restrict__ Z,
          float* __restrict__ H,
          int M)
{
    const int ASTR = 20, BSTR = 133;
    __shared__ u32 Ah[128 * ASTR];
    __shared__ u32 Al[128 * ASTR];
    __shared__ u32 Bh[16 * BSTR];
    __shared__ u32 Bl[16 * BSTR];

    const int tid   = threadIdx.x;
    const int wid   = tid >> 5;
    const int lane  = tid & 31;
    const int grp   = lane >> 2;      // 0..7
    const int tig   = lane & 3;       // 0..3
    const int warpM = wid >> 1;       // 0..3  (32-row strip)
    const int warpN = wid & 1;        // 0..1  (64-col strip)
    const int row0  = blockIdx.x * 128;
    const bool relHalf = (blockIdx.y == 0);
    const float* __restrict__ W = relHalf ? Wrel : Wroot;

    float acc[2][8][4];
    #pragma unroll
    for (int mt = 0; mt < 2; mt++)
        #pragma unroll
        for (int nt = 0; nt < 8; nt++)
            #pragma unroll
            for (int c = 0; c < 4; c++) acc[mt][nt][c] = 0.f;

    for (int k0 = 0; k0 < 128; k0 += 16) {
        // ---- load A tile: 128 rows x 16 k  (512 float4, 2 per thread) ----
        #pragma unroll
        for (int j = 0; j < 2; j++) {
            int idx = tid + j * 256;
            int r   = idx >> 2;
            int kq  = idx & 3;
            int gr  = row0 + r;
            float4 a = make_float4(0.f, 0.f, 0.f, 0.f);
            if (gr < M) a = *(const float4*)(A + (size_t)gr * 128 + k0 + kq * 4);
            if (RELU) {
                a.x = fmaxf(a.x, 0.f); a.y = fmaxf(a.y, 0.f);
                a.z = fmaxf(a.z, 0.f); a.w = fmaxf(a.w, 0.f);
            }
            float av[4] = {a.x, a.y, a.z, a.w};
            #pragma unroll
            for (int c = 0; c < 4; c++) {
                u32 hb = f2tf32(av[c]);
                float hf = __uint_as_float(hb);
                u32 lb = f2tf32(av[c] - hf);
                Ah[r * ASTR + kq * 4 + c] = hb;
                Al[r * ASTR + kq * 4 + c] = lb;
            }
        }
        // ---- load B tile: 16 k x 128 n  (512 float4, 2 per thread) ----
        #pragma unroll
        for (int j = 0; j < 2; j++) {
            int idx = tid + j * 256;
            int kr  = idx >> 5;               // 0..15
            int nq  = idx & 31;               // float4 col 0..31
            float4 b = *(const float4*)(W + (size_t)(k0 + kr) * 128 + nq * 4);
            float bv[4] = {b.x, b.y, b.z, b.w};
            #pragma unroll
            for (int c = 0; c < 4; c++) {
                u32 hb = f2tf32(bv[c]);
                float hf = __uint_as_float(hb);
                u32 lb = f2tf32(bv[c] - hf);
                Bh[kr * BSTR + nq * 4 + c] = hb;
                Bl[kr * BSTR + nq * 4 + c] = lb;
            }
        }
        __syncthreads();

        // ---- 2 k-steps of 8 ----
        #pragma unroll
        for (int ks = 0; ks < 2; ks++) {
            const int k = ks * 8;
            u32 ah[2][4], al[2][4], bh[8][2], bl[8][2];
            #pragma unroll
            for (int mt = 0; mt < 2; mt++) {
                int m  = warpM * 32 + mt * 16 + grp;
                int b0 = m * ASTR + k + tig;
                ah[mt][0] = Ah[b0];
                ah[mt][1] = Ah[b0 + 8 * ASTR];
                ah[mt][2] = Ah[b0 + 4];
                ah[mt][3] = Ah[b0 + 8 * ASTR + 4];
                al[mt][0] = Al[b0];
                al[mt][1] = Al[b0 + 8 * ASTR];
                al[mt][2] = Al[b0 + 4];
                al[mt][3] = Al[b0 + 8 * ASTR + 4];
            }
            #pragma unroll
            for (int nt = 0; nt < 8; nt++) {
                int n  = warpN * 64 + nt * 8 + grp;
                int b0 = (k + tig) * BSTR + n;
                bh[nt][0] = Bh[b0];
                bh[nt][1] = Bh[b0 + 4 * BSTR];
                bl[nt][0] = Bl[b0];
                bl[nt][1] = Bl[b0 + 4 * BSTR];
            }
            #pragma unroll
            for (int mt = 0; mt < 2; mt++)
                #pragma unroll
                for (int nt = 0; nt < 8; nt++) {
                    mma_tf32(acc[mt][nt], ah[mt], bh[nt]);   // hi*hi
                    mma_tf32(acc[mt][nt], ah[mt], bl[nt]);   // hi*lo
                    mma_tf32(acc[mt][nt], al[mt], bh[nt]);   // lo*hi
                }
        }
        __syncthreads();
    }

    // ---- epilogue ----
    #pragma unroll
    for (int mt = 0; mt < 2; mt++) {
        int r0 = row0 + warpM * 32 + mt * 16 + grp;
        int r1 = r0 + 8;
        #pragma unroll
        for (int nt = 0; nt < 8; nt++) {
            int c = warpN * 64 + nt * 8 + 2 * tig;   // 0..126
            if (relHalf) {
                if (r0 < M) *(float2*)(Z + (size_t)r0 * 128 + c) =
                    make_float2(acc[mt][nt][0], acc[mt][nt][1]);
                if (r1 < M) *(float2*)(Z + (size_t)r1 * 128 + c) =
                    make_float2(acc[mt][nt][2], acc[mt][nt][3]);
            } else {
                float bx = bias[c], by = bias[c + 1];
                if (r0 < M) *(float2*)(H + (size_t)r0 * 128 + c) =
                    make_float2(acc[mt][nt][0] + bx, acc[mt][nt][1] + by);
                if (r1 < M) *(float2*)(H + (size_t)r1 * 128 + c) =
                    make_float2(acc[mt][nt][2] + bx, acc[mt][nt][3] + by);
            }
        }
    }
}

// ---------------------------------------------------------------------------
// CSR gather: one warp per dst node, 8-way unrolled, no atomics.
// ---------------------------------------------------------------------------
__global__ void __launch_bounds__(256)
gather_kernel(const float* __restrict__ Z,
              float* __restrict__ H,
              int Nn)
{
    int warp = (int)((blockIdx.x * (unsigned)blockDim.x + threadIdx.x) >> 5);
    int lane = threadIdx.x & 31;
    if (warp >= Nn) return;

    int lo = g_off[warp];
    int hi = g_off[warp + 1];
    if (lo == hi) return;

    float4 acc = make_float4(0.f, 0.f, 0.f, 0.f);
    int e = lo;
    for (; e + 7 < hi; e += 8) {
        int   s[8]; float w[8]; float4 v[8];
        #pragma unroll
        for (int j = 0; j < 8; j++) { s[j] = g_src[e + j]; w[j] = g_wp[e + j]; }
        #pragma unroll
        for (int j = 0; j < 8; j++)
            v[j] = ((const float4*)(Z + (size_t)s[j] * 128))[lane];
        #pragma unroll
        for (int j = 0; j < 8; j++) {
            acc.x = fmaf(w[j], v[j].x, acc.x);
            acc.y = fmaf(w[j], v[j].y, acc.y);
            acc.z = fmaf(w[j], v[j].z, acc.z);
            acc.w = fmaf(w[j], v[j].w, acc.w);
        }
    }
    for (; e < hi; e++) {
        int   s0 = g_src[e];
        float w0 = g_wp[e];
        float4 v0 = ((const float4*)(Z + (size_t)s0 * 128))[lane];
        acc.x = fmaf(w0, v0.x, acc.x); acc.y = fmaf(w0, v0.y, acc.y);
        acc.z = fmaf(w0, v0.z, acc.z); acc.w = fmaf(w0, v0.w, acc.w);
    }

    float4* hp = ((float4*)(H + (size_t)warp * 128)) + lane;
    float4 h = *hp;
    h.x += acc.x; h.y += acc.y; h.z += acc.z; h.w += acc.w;
    *hp = h;
}

// ---------------------------------------------------------------------------
// Pool + linear + sigmoid; re-zeroes g_deg for the next call.
// ---------------------------------------------------------------------------
__global__ void __launch_bounds__(128)
pool_kernel(const float* __restrict__ H2,
            const float* __restrict__ Wlin,
            const float* __restrict__ blin,
            float* __restrict__ out,
            int Nn)
{
    int g = blockIdx.x;
    int t = threadIdx.x;

    for (int i = g * 128 + t; i < Nn; i += gridDim.x * 128)
        g_deg[i] = 0;

    __shared__ int s_range[2];
    if (t < 2) {
        int target = g + t;
        int lo = 0, hi = Nn;
        while (lo < hi) {
            int mid = (lo + hi) >> 1;
            if (g_batch[mid] < target) lo = mid + 1; else hi = mid;
        }
        s_range[t] = lo;
    }
    __syncthreads();
    int lo = s_range[0], hi = s_range[1];

    float m = -INFINITY;
    for (int n = lo; n < hi; n++)
        m = fmaxf(m, H2[(size_t)n * 128 + t]);
    if (hi > lo) m = fmaxf(m, 0.0f);

    float v = m * Wlin[t];

    __shared__ float red[128];
    red[t] = v;
    __syncthreads();
    #pragma unroll
    for (int s = 64; s > 0; s >>= 1) {
        if (t < s) red[t] += red[t + s];
        __syncthreads();
    }
    if (t == 0) {
        float logit = red[0] + blin[0];
        out[g] = 1.0f / (1.0f + expf(-logit));
    }
}

// ---------------------------------------------------------------------------
extern "C" void kernel_launch(void* const* d_in, const int* in_sizes, int n_in,
                              void* d_out, int out_size)
{
    const float* x      = (const float*) d_in[0];
    const int*   ei     = (const int*)   d_in[1];
    const int*   batch  = (const int*)   d_in[2];
    const float* ew     = (const float*) d_in[3];
    const float* W1rel  = (const float*) d_in[4];
    const float* b1     = (const float*) d_in[5];
    const float* W1root = (const float*) d_in[6];
    const float* W2rel  = (const float*) d_in[7];
    const float* b2     = (const float*) d_in[8];
    const float* W2root = (const float*) d_in[9];
    const float* Wlin   = (const float*) d_in[10];
    const float* blin   = (const float*) d_in[11];
    float* out = (float*)d_out;

    int M = in_sizes[0] / 128;
    int E = in_sizes[1] / 2;
    int G = out_size;
    if (M > MAX_NODES) M = MAX_NODES;
    if (E > MAX_EDGES) E = MAX_EDGES;

    float *Z, *H1, *H2;
    cudaGetSymbolAddress((void**)&Z,  g_Z);
    cudaGetSymbolAddress((void**)&H1, g_H1);
    cudaGetSymbolAddress((void**)&H2, g_H2);

    int NB = (M + SCAN_CHUNK - 1) / SCAN_CHUNK;
    dim3 ggrid((M + 127) / 128, 2);
    int gatherBlocks = (M * 32 + 255) / 256;

    // 1: convert + detect + histogram
    {
        int work = 2 * E;
        if (M > work) work = M;
        convert_hist<<<(work + 255) / 256, 256>>>(ei, batch, E, M);
    }
    // 2-3: scan front half
    partial_kernel  <<<NB, 256>>>(M);
    scan_part_kernel<<<1, 64>>>(NB, M);
    // 4: Layer-1 GEMM (no CSR dependence) -- profiled launch
    gemm_dual<false><<<ggrid, 256>>>(x, W1rel, W1root, b1, Z, H1, M);
    // 5-6: finish CSR build
    writeoff_kernel <<<NB, 256>>>(M);
    fill_kernel<<<(E + 255) / 256, 256>>>(ew, E, M);
    // 7: Layer-1 gather
    gather_kernel<<<gatherBlocks, 256>>>(Z, H1, M);
    // 8-9: Layer 2
    gemm_dual<true><<<ggrid, 256>>>(H1, W2rel, W2root, b2, Z, H2, M);
    gather_kernel<<<gatherBlocks, 256>>>(Z, H2, M);
    // 10: Pool + linear + sigmoid (+ deg re-zero)
    pool_kernel<<<G, 128>>>(H2, Wlin, blin, out, M);
}

// round 10
// speedup vs baseline: 1.9521x; 1.1041x over previous
#include <cuda_runtime.h>
#include <math.h>

// ---------------------------------------------------------------------------
// simpleGNN: 2x GraphConv(128->128) + ReLU, segment_max pool, Linear(128->1),
// sigmoid.
// GEMM-first reordering; CSR gather (no float atomics); parallel CSR build.
// R10 == R9 (infra failure last round, re-bench): GEMM smem holds ONE fp32
// plane per operand; split-TF32 hi/lo conversion happens in registers at
// fragment-load time (halves LDS traffic, which R8 ncu showed as the
// bottleneck: L1=68.3%, tensor=37.5%).
// ---------------------------------------------------------------------------

#define MAX_NODES 50000
#define MAX_EDGES 640000
#define FDIM      128
#define SCAN_CHUNK 1024
#define MAX_PARTS  64

typedef unsigned int u32;

__device__ float g_Z    [MAX_NODES * FDIM];
__device__ float g_H1   [MAX_NODES * FDIM];
__device__ float g_H2   [MAX_NODES * FDIM];
__device__ int   g_ei   [2 * MAX_EDGES];
__device__ int   g_batch[MAX_NODES];
__device__ int   g_deg  [MAX_NODES];
__device__ int   g_off  [MAX_NODES + 1];
__device__ int   g_part [MAX_PARTS];
__device__ int   g_src  [MAX_EDGES];
__device__ float g_wp   [MAX_EDGES];

// ---------------- tf32 helpers ---------------------------------------------
__device__ __forceinline__ u32 f2tf32(float f) {
    u32 u;
    asm("cvt.rna.tf32.f32 %0, %1;" : "=r"(u) : "f"(f));
    return u;
}
__device__ __forceinline__ void split_tf32(float f, u32& hi, u32& lo) {
    hi = f2tf32(f);
    lo = f2tf32(f - __uint_as_float(hi));
}
__device__ __forceinline__ void mma_tf32(float c[4], const u32 a[4], const u32 b[2]) {
    asm volatile(
        "mma.sync.aligned.m16n8k8.row.col.f32.tf32.tf32.f32 "
        "{%0,%1,%2,%3}, {%4,%5,%6,%7}, {%8,%9}, {%0,%1,%2,%3};"
        : "+f"(c[0]), "+f"(c[1]), "+f"(c[2]), "+f"(c[3])
        : "r"(a[0]), "r"(a[1]), "r"(a[2]), "r"(a[3]), "r"(b[0]), "r"(b[1]));
}

// ---------------------------------------------------------------------------
// convert + histogram + dtype detect (fused).
// ---------------------------------------------------------------------------
__global__ void __launch_bounds__(256)
convert_hist(const int* __restrict__ ei,
             const int* __restrict__ batch,
             int E, int Nn)
{
    __shared__ int s_is64;
    if (threadIdx.x == 0) {
        int any = 0;
        #pragma unroll
        for (int k = 1; k < 128; k += 2) any |= ei[k];
        s_is64 = (any == 0);
    }
    __syncthreads();
    int f = s_is64;

    int i = blockIdx.x * blockDim.x + threadIdx.x;
    int twoE = 2 * E;
    if (i < twoE) {
        int v = f ? ei[2 * i] : ei[i];
        g_ei[i] = v;
        if (i >= E && (unsigned)v < (unsigned)Nn)
            atomicAdd(&g_deg[v], 1);
    }
    if (i < Nn)
        g_batch[i] = f ? batch[2 * i] : batch[i];
}

// ---------------------------------------------------------------------------
// Blocked exclusive scan of g_deg -> g_off.
// ---------------------------------------------------------------------------
__global__ void __launch_bounds__(256)
partial_kernel(int Nn)
{
    __shared__ int red[256];
    int t = threadIdx.x;
    int base = blockIdx.x * SCAN_CHUNK + t * 4;
    int s = 0;
    #pragma unroll
    for (int j = 0; j < 4; j++) {
        int idx = base + j;
        s += (idx < Nn) ? g_deg[idx] : 0;
    }
    red[t] = s;
    __syncthreads();
    #pragma unroll
    for (int d = 128; d > 0; d >>= 1) {
        if (t < d) red[t] += red[t + d];
        __syncthreads();
    }
    if (t == 0) g_part[blockIdx.x] = red[0];
}

__global__ void __launch_bounds__(64)
scan_part_kernel(int NB, int Nn)
{
    __shared__ int s[MAX_PARTS];
    int t = threadIdx.x;
    s[t] = (t < NB) ? g_part[t] : 0;
    __syncthreads();
    #pragma unroll
    for (int d = 1; d < MAX_PARTS; d <<= 1) {
        int v = (t >= d) ? s[t - d] : 0;
        __syncthreads();
        s[t] += v;
        __syncthreads();
    }
    if (t < NB) g_part[t] = (t == 0) ? 0 : s[t - 1];
    if (t == MAX_PARTS - 1) g_off[Nn] = s[MAX_PARTS - 1];
}

__global__ void __launch_bounds__(256)
writeoff_kernel(int Nn)
{
    __shared__ int sums[256];
    int t = threadIdx.x;
    int base = blockIdx.x * SCAN_CHUNK + t * 4;

    int local[4];
    int s = 0;
    #pragma unroll
    for (int j = 0; j < 4; j++) {
        int idx = base + j;
        local[j] = (idx < Nn) ? g_deg[idx] : 0;
        s += local[j];
    }
    sums[t] = s;
    __syncthreads();
    #pragma unroll
    for (int d = 1; d < 256; d <<= 1) {
        int v = (t >= d) ? sums[t - d] : 0;
        __syncthreads();
        sums[t] += v;
        __syncthreads();
    }
    int run = g_part[blockIdx.x] + ((t == 0) ? 0 : sums[t - 1]);
    #pragma unroll
    for (int j = 0; j < 4; j++) {
        int idx = base + j;
        if (idx < Nn) {
            g_off[idx] = run;
            g_deg[idx] = run;
            run += local[j];
        }
    }
}

__global__ void __launch_bounds__(256)
fill_kernel(const float* __restrict__ ew, int E, int Nn)
{
    int i = blockIdx.x * blockDim.x + threadIdx.x;
    if (i >= E) return;
    int s = g_ei[i];
    int d = g_ei[E + i];
    if ((unsigned)s >= (unsigned)Nn || (unsigned)d >= (unsigned)Nn) return;
    int p = atomicAdd(&g_deg[d], 1);
    g_src[p] = s;
    g_wp[p]  = ew[i];
}

// ---------------------------------------------------------------------------
// Dual-output GEMM on tensor cores (split-TF32 in registers, 3 mma terms).
//   y==0: Z[m,:] = act(A[m,:]) @ Wrel       (cols 0..127)
//   y==1: H[m,:] = act(A[m,:]) @ Wroot + b  (cols 128..255)
// Block tile 128x128, BK=16, 256 threads (8 warps: 4m x 2n, warp tile 32x64).
// Smem: ONE fp32 plane per operand (A stride 20, B stride 133; both verified
// conflict-free for the fragment access patterns).  hi/lo split via cvt in
// registers at fragment-load time.
// ---------------------------------------------------------------------------
template<bool RELU>
__global__ void __launch_bounds__(256)
gemm_dual(const float* __restrict__ A,
          const float* __restrict__ Wrel,
          const float* __restrict__ Wroot,
          const float* __restrict__ bias,
          float* __restrict__ Z,
          float* __restrict__ H,
          int M)
{
    const int ASTR = 20, BSTR = 133;
    __shared__ __align__(16) float As[128 * ASTR];
    __shared__ float Bs[16 * BSTR];

    const int tid   = threadIdx.x;
    const int wid   = tid >> 5;
    const int lane  = tid & 31;
    const int grp   = lane >> 2;      // 0..7
    const int tig   = lane & 3;       // 0..3
    const int warpM = wid >> 1;       // 0..3  (32-row strip)
    const int warpN = wid & 1;        // 0..1  (64-col strip)
    const int row0  = blockIdx.x * 128;
    const bool relHalf = (blockIdx.y == 0);
    const float* __restrict__ W = relHalf ? Wrel : Wroot;

    float acc[2][8][4];
    #pragma unroll
    for (int mt = 0; mt < 2; mt++)
        #pragma unroll
        for (int nt = 0; nt < 8; nt++)
            #pragma unroll
            for (int c = 0; c < 4; c++) acc[mt][nt][c] = 0.f;

    for (int k0 = 0; k0 < 128; k0 += 16) {
        // ---- load A tile: 128 rows x 16 k  (512 float4, 2 per thread) ----
        #pragma unroll
        for (int j = 0; j < 2; j++) {
            int idx = tid + j * 256;
            int r   = idx >> 2;
            int kq  = idx & 3;
            int gr  = row0 + r;
            float4 a = make_float4(0.f, 0.f, 0.f, 0.f);
            if (gr < M) a = *(const float4*)(A + (size_t)gr * 128 + k0 + kq * 4);
            if (RELU) {
                a.x = fmaxf(a.x, 0.f); a.y = fmaxf(a.y, 0.f);
                a.z = fmaxf(a.z, 0.f); a.w = fmaxf(a.w, 0.f);
            }
            *(float4*)&As[r * ASTR + kq * 4] = a;   // 80r+16kq bytes: 16B aligned
        }
        // ---- load B tile: 16 k x 128 n  (512 float4, 2 per thread) ----
        #pragma unroll
        for (int j = 0; j < 2; j++) {
            int idx = tid + j * 256;
            int kr  = idx >> 5;               // 0..15
            int nq  = idx & 31;               // float4 col 0..31
            float4 b = *(const float4*)(W + (size_t)(k0 + kr) * 128 + nq * 4);
            int base = kr * BSTR + nq * 4;    // BSTR odd -> scalar stores
            Bs[base + 0] = b.x;
            Bs[base + 1] = b.y;
            Bs[base + 2] = b.z;
            Bs[base + 3] = b.w;
        }
        __syncthreads();

        // ---- 2 k-steps of 8 ----
        #pragma unroll
        for (int ks = 0; ks < 2; ks++) {
            const int k = ks * 8;
            u32 ah[2][4], al[2][4], bh[8][2], bl[8][2];
            #pragma unroll
            for (int mt = 0; mt < 2; mt++) {
                int m  = warpM * 32 + mt * 16 + grp;
                int b0 = m * ASTR + k + tig;
                float f0 = As[b0];
                float f1 = As[b0 + 8 * ASTR];
                float f2 = As[b0 + 4];
                float f3 = As[b0 + 8 * ASTR + 4];
                split_tf32(f0, ah[mt][0], al[mt][0]);
                split_tf32(f1, ah[mt][1], al[mt][1]);
                split_tf32(f2, ah[mt][2], al[mt][2]);
                split_tf32(f3, ah[mt][3], al[mt][3]);
            }
            #pragma unroll
            for (int nt = 0; nt < 8; nt++) {
                int n  = warpN * 64 + nt * 8 + grp;
                int b0 = (k + tig) * BSTR + n;
                float f0 = Bs[b0];
                float f1 = Bs[b0 + 4 * BSTR];
                split_tf32(f0, bh[nt][0], bl[nt][0]);
                split_tf32(f1, bh[nt][1], bl[nt][1]);
            }
            #pragma unroll
            for (int mt = 0; mt < 2; mt++)
                #pragma unroll
                for (int nt = 0; nt < 8; nt++) {
                    mma_tf32(acc[mt][nt], ah[mt], bh[nt]);   // hi*hi
                    mma_tf32(acc[mt][nt], ah[mt], bl[nt]);   // hi*lo
                    mma_tf32(acc[mt][nt], al[mt], bh[nt]);   // lo*hi
                }
        }
        __syncthreads();
    }

    // ---- epilogue ----
    #pragma unroll
    for (int mt = 0; mt < 2; mt++) {
        int r0 = row0 + warpM * 32 + mt * 16 + grp;
        int r1 = r0 + 8;
        #pragma unroll
        for (int nt = 0; nt < 8; nt++) {
            int c = warpN * 64 + nt * 8 + 2 * tig;   // 0..126
            if (relHalf) {
                if (r0 < M) *(float2*)(Z + (size_t)r0 * 128 + c) =
                    make_float2(acc[mt][nt][0], acc[mt][nt][1]);
                if (r1 < M) *(float2*)(Z + (size_t)r1 * 128 + c) =
                    make_float2(acc[mt][nt][2], acc[mt][nt][3]);
            } else {
                float bx = bias[c], by = bias[c + 1];
                if (r0 < M) *(float2*)(H + (size_t)r0 * 128 + c) =
                    make_float2(acc[mt][nt][0] + bx, acc[mt][nt][1] + by);
                if (r1 < M) *(float2*)(H + (size_t)r1 * 128 + c) =
                    make_float2(acc[mt][nt][2] + bx, acc[mt][nt][3] + by);
            }
        }
    }
}

// ---------------------------------------------------------------------------
// CSR gather: one warp per dst node, 8-way unrolled, no atomics.
// ---------------------------------------------------------------------------
__global__ void __launch_bounds__(256)
gather_kernel(const float* __restrict__ Z,
              float* __restrict__ H,
              int Nn)
{
    int warp = (int)((blockIdx.x * (unsigned)blockDim.x + threadIdx.x) >> 5);
    int lane = threadIdx.x & 31;
    if (warp >= Nn) return;

    int lo = g_off[warp];
    int hi = g_off[warp + 1];
    if (lo == hi) return;

    float4 acc = make_float4(0.f, 0.f, 0.f, 0.f);
    int e = lo;
    for (; e + 7 < hi; e += 8) {
        int   s[8]; float w[8]; float4 v[8];
        #pragma unroll
        for (int j = 0; j < 8; j++) { s[j] = g_src[e + j]; w[j] = g_wp[e + j]; }
        #pragma unroll
        for (int j = 0; j < 8; j++)
            v[j] = ((const float4*)(Z + (size_t)s[j] * 128))[lane];
        #pragma unroll
        for (int j = 0; j < 8; j++) {
            acc.x = fmaf(w[j], v[j].x, acc.x);
            acc.y = fmaf(w[j], v[j].y, acc.y);
            acc.z = fmaf(w[j], v[j].z, acc.z);
            acc.w = fmaf(w[j], v[j].w, acc.w);
        }
    }
    for (; e < hi; e++) {
        int   s0 = g_src[e];
        float w0 = g_wp[e];
        float4 v0 = ((const float4*)(Z + (size_t)s0 * 128))[lane];
        acc.x = fmaf(w0, v0.x, acc.x); acc.y = fmaf(w0, v0.y, acc.y);
        acc.z = fmaf(w0, v0.z, acc.z); acc.w = fmaf(w0, v0.w, acc.w);
    }

    float4* hp = ((float4*)(H + (size_t)warp * 128)) + lane;
    float4 h = *hp;
    h.x += acc.x; h.y += acc.y; h.z += acc.z; h.w += acc.w;
    *hp = h;
}

// ---------------------------------------------------------------------------
// Pool + linear + sigmoid; re-zeroes g_deg for the next call.
// ---------------------------------------------------------------------------
__global__ void __launch_bounds__(128)
pool_kernel(const float* __restrict__ H2,
            const float* __restrict__ Wlin,
            const float* __restrict__ blin,
            float* __restrict__ out,
            int Nn)
{
    int g = blockIdx.x;
    int t = threadIdx.x;

    for (int i = g * 128 + t; i < Nn; i += gridDim.x * 128)
        g_deg[i] = 0;

    __shared__ int s_range[2];
    if (t < 2) {
        int target = g + t;
        int lo = 0, hi = Nn;
        while (lo < hi) {
            int mid = (lo + hi) >> 1;
            if (g_batch[mid] < target) lo = mid + 1; else hi = mid;
        }
        s_range[t] = lo;
    }
    __syncthreads();
    int lo = s_range[0], hi = s_range[1];

    float m = -INFINITY;
    for (int n = lo; n < hi; n++)
        m = fmaxf(m, H2[(size_t)n * 128 + t]);
    if (hi > lo) m = fmaxf(m, 0.0f);

    float v = m * Wlin[t];

    __shared__ float red[128];
    red[t] = v;
    __syncthreads();
    #pragma unroll
    for (int s = 64; s > 0; s >>= 1) {
        if (t < s) red[t] += red[t + s];
        __syncthreads();
    }
    if (t == 0) {
        float logit = red[0] + blin[0];
        out[g] = 1.0f / (1.0f + expf(-logit));
    }
}

// ---------------------------------------------------------------------------
extern "C" void kernel_launch(void* const* d_in, const int* in_sizes, int n_in,
                              void* d_out, int out_size)
{
    const float* x      = (const float*) d_in[0];
    const int*   ei     = (const int*)   d_in[1];
    const int*   batch  = (const int*)   d_in[2];
    const float* ew     = (const float*) d_in[3];
    const float* W1rel  = (const float*) d_in[4];
    const float* b1     = (const float*) d_in[5];
    const float* W1root = (const float*) d_in[6];
    const float* W2rel  = (const float*) d_in[7];
    const float* b2     = (const float*) d_in[8];
    const float* W2root = (const float*) d_in[9];
    const float* Wlin   = (const float*) d_in[10];
    const float* blin   = (const float*) d_in[11];
    float* out = (float*)d_out;

    int M = in_sizes[0] / 128;
    int E = in_sizes[1] / 2;
    int G = out_size;
    if (M > MAX_NODES) M = MAX_NODES;
    if (E > MAX_EDGES) E = MAX_EDGES;

    float *Z, *H1, *H2;
    cudaGetSymbolAddress((void**)&Z,  g_Z);
    cudaGetSymbolAddress((void**)&H1, g_H1);
    cudaGetSymbolAddress((void**)&H2, g_H2);

    int NB = (M + SCAN_CHUNK - 1) / SCAN_CHUNK;
    dim3 ggrid((M + 127) / 128, 2);
    int gatherBlocks = (M * 32 + 255) / 256;

    // 1: convert + detect + histogram
    {
        int work = 2 * E;
        if (M > work) work = M;
        convert_hist<<<(work + 255) / 256, 256>>>(ei, batch, E, M);
    }
    // 2-3: scan front half
    partial_kernel  <<<NB, 256>>>(M);
    scan_part_kernel<<<1, 64>>>(NB, M);
    // 4: Layer-1 GEMM (no CSR dependence) -- profiled launch
    gemm_dual<false><<<ggrid, 256>>>(x, W1rel, W1root, b1, Z, H1, M);
    // 5-6: finish CSR build
    writeoff_kernel <<<NB, 256>>>(M);
    fill_kernel<<<(E + 255) / 256, 256>>>(ew, E, M);
    // 7: Layer-1 gather
    gather_kernel<<<gatherBlocks, 256>>>(Z, H1, M);
    // 8-9: Layer 2
    gemm_dual<true><<<ggrid, 256>>>(H1, W2rel, W2root, b2, Z, H2, M);
    gather_kernel<<<gatherBlocks, 256>>>(Z, H2, M);
    // 10: Pool + linear + sigmoid (+ deg re-zero)
    pool_kernel<<<G, 128>>>(H2, Wlin, blin, out, M);
}

// round 12
// speedup vs baseline: 1.9679x; 1.0081x over previous
#include <cuda_runtime.h>
#include <math.h>

// ---------------------------------------------------------------------------
// simpleGNN: 2x GraphConv(128->128) + ReLU, segment_max pool, Linear(128->1),
// sigmoid.
// GEMM-first reordering; CSR gather (no float atomics); parallel CSR build.
// R12 == R11 (infra failure last round, re-bench; static guard removed):
//   GEMM latency removal -- B weight tile resident in smem for the whole
//   block (loaded once), A tile double-buffered via cp.async.  R10 ncu:
//   nothing saturated (issue 38.6%, tensor 43.6%) => per-tile global-load
//   latency was exposed at each __syncthreads.
// ---------------------------------------------------------------------------

#define MAX_NODES 50000
#define MAX_EDGES 640000
#define FDIM      128
#define SCAN_CHUNK 1024
#define MAX_PARTS  64

#define ASTR 20
#define BSTR 133
#define A_TILE (128 * ASTR)                  // floats per A buffer
#define GEMM_SMEM_FLOATS (128 * BSTR + 2 * A_TILE)
#define GEMM_SMEM_BYTES  (GEMM_SMEM_FLOATS * 4)

typedef unsigned int u32;

__device__ float g_Z    [MAX_NODES * FDIM];
__device__ float g_H1   [MAX_NODES * FDIM];
__device__ float g_H2   [MAX_NODES * FDIM];
__device__ int   g_ei   [2 * MAX_EDGES];
__device__ int   g_batch[MAX_NODES];
__device__ int   g_deg  [MAX_NODES];
__device__ int   g_off  [MAX_NODES + 1];
__device__ int   g_part [MAX_PARTS];
__device__ int   g_src  [MAX_EDGES];
__device__ float g_wp   [MAX_EDGES];

// ---------------- tf32 helpers ---------------------------------------------
__device__ __forceinline__ u32 f2tf32(float f) {
    u32 u;
    asm("cvt.rna.tf32.f32 %0, %1;" : "=r"(u) : "f"(f));
    return u;
}
__device__ __forceinline__ void split_tf32(float f, u32& hi, u32& lo) {
    hi = f2tf32(f);
    lo = f2tf32(f - __uint_as_float(hi));
}
__device__ __forceinline__ void mma_tf32(float c[4], const u32 a[4], const u32 b[2]) {
    asm volatile(
        "mma.sync.aligned.m16n8k8.row.col.f32.tf32.tf32.f32 "
        "{%0,%1,%2,%3}, {%4,%5,%6,%7}, {%8,%9}, {%0,%1,%2,%3};"
        : "+f"(c[0]), "+f"(c[1]), "+f"(c[2]), "+f"(c[3])
        : "r"(a[0]), "r"(a[1]), "r"(a[2]), "r"(a[3]), "r"(b[0]), "r"(b[1]));
}
__device__ __forceinline__ void cp_async16(u32 smem_dst, const void* gsrc, int src_bytes) {
    asm volatile("cp.async.ca.shared.global [%0], [%1], 16, %2;"
                 :: "r"(smem_dst), "l"(gsrc), "r"(src_bytes));
}
__device__ __forceinline__ void cp_async_commit() {
    asm volatile("cp.async.commit_group;");
}
__device__ __forceinline__ void cp_async_wait0() {
    asm volatile("cp.async.wait_group 0;");
}

// ---------------------------------------------------------------------------
// convert + histogram + dtype detect (fused).
// ---------------------------------------------------------------------------
__global__ void __launch_bounds__(256)
convert_hist(const int* __restrict__ ei,
             const int* __restrict__ batch,
             int E, int Nn)
{
    __shared__ int s_is64;
    if (threadIdx.x == 0) {
        int any = 0;
        #pragma unroll
        for (int k = 1; k < 128; k += 2) any |= ei[k];
        s_is64 = (any == 0);
    }
    __syncthreads();
    int f = s_is64;

    int i = blockIdx.x * blockDim.x + threadIdx.x;
    int twoE = 2 * E;
    if (i < twoE) {
        int v = f ? ei[2 * i] : ei[i];
        g_ei[i] = v;
        if (i >= E && (unsigned)v < (unsigned)Nn)
            atomicAdd(&g_deg[v], 1);
    }
    if (i < Nn)
        g_batch[i] = f ? batch[2 * i] : batch[i];
}

// ---------------------------------------------------------------------------
// Blocked exclusive scan of g_deg -> g_off.
// ---------------------------------------------------------------------------
__global__ void __launch_bounds__(256)
partial_kernel(int Nn)
{
    __shared__ int red[256];
    int t = threadIdx.x;
    int base = blockIdx.x * SCAN_CHUNK + t * 4;
    int s = 0;
    #pragma unroll
    for (int j = 0; j < 4; j++) {
        int idx = base + j;
        s += (idx < Nn) ? g_deg[idx] : 0;
    }
    red[t] = s;
    __syncthreads();
    #pragma unroll
    for (int d = 128; d > 0; d >>= 1) {
        if (t < d) red[t] += red[t + d];
        __syncthreads();
    }
    if (t == 0) g_part[blockIdx.x] = red[0];
}

__global__ void __launch_bounds__(64)
scan_part_kernel(int NB, int Nn)
{
    __shared__ int s[MAX_PARTS];
    int t = threadIdx.x;
    s[t] = (t < NB) ? g_part[t] : 0;
    __syncthreads();
    #pragma unroll
    for (int d = 1; d < MAX_PARTS; d <<= 1) {
        int v = (t >= d) ? s[t - d] : 0;
        __syncthreads();
        s[t] += v;
        __syncthreads();
    }
    if (t < NB) g_part[t] = (t == 0) ? 0 : s[t - 1];
    if (t == MAX_PARTS - 1) g_off[Nn] = s[MAX_PARTS - 1];
}

__global__ void __launch_bounds__(256)
writeoff_kernel(int Nn)
{
    __shared__ int sums[256];
    int t = threadIdx.x;
    int base = blockIdx.x * SCAN_CHUNK + t * 4;

    int local[4];
    int s = 0;
    #pragma unroll
    for (int j = 0; j < 4; j++) {
        int idx = base + j;
        local[j] = (idx < Nn) ? g_deg[idx] : 0;
        s += local[j];
    }
    sums[t] = s;
    __syncthreads();
    #pragma unroll
    for (int d = 1; d < 256; d <<= 1) {
        int v = (t >= d) ? sums[t - d] : 0;
        __syncthreads();
        sums[t] += v;
        __syncthreads();
    }
    int run = g_part[blockIdx.x] + ((t == 0) ? 0 : sums[t - 1]);
    #pragma unroll
    for (int j = 0; j < 4; j++) {
        int idx = base + j;
        if (idx < Nn) {
            g_off[idx] = run;
            g_deg[idx] = run;
            run += local[j];
        }
    }
}

__global__ void __launch_bounds__(256)
fill_kernel(const float* __restrict__ ew, int E, int Nn)
{
    int i = blockIdx.x * blockDim.x + threadIdx.x;
    if (i >= E) return;
    int s = g_ei[i];
    int d = g_ei[E + i];
    if ((unsigned)s >= (unsigned)Nn || (unsigned)d >= (unsigned)Nn) return;
    int p = atomicAdd(&g_deg[d], 1);
    g_src[p] = s;
    g_wp[p]  = ew[i];
}

// ---------------------------------------------------------------------------
// Dual-output GEMM on tensor cores (split-TF32 in registers, 3 mma terms).
//   y==0: Z[m,:] = act(A[m,:]) @ Wrel       (cols 0..127)
//   y==1: H[m,:] = act(A[m,:]) @ Wroot + b  (cols 128..255)
// Block tile 128x128, BK=16, 256 threads (8 warps: 4m x 2n, warp tile 32x64).
// Dynamic smem: B resident for whole block (128x128 fp32, stride 133,
// conflict-free), A double-buffered via cp.async (stride 20).  ReLU applied
// at fragment-load time (cp.async copies raw bytes).
// ---------------------------------------------------------------------------
template<bool RELU>
__global__ void __launch_bounds__(256)
gemm_dual(const float* __restrict__ A,
          const float* __restrict__ Wrel,
          const float* __restrict__ Wroot,
          const float* __restrict__ bias,
          float* __restrict__ Z,
          float* __restrict__ H,
          int M)
{
    extern __shared__ __align__(16) float smem[];
    float* Bs = smem;                      // 128 * BSTR
    float* As = smem + 128 * BSTR;         // 2 * A_TILE

    const int tid   = threadIdx.x;
    const int wid   = tid >> 5;
    const int lane  = tid & 31;
    const int grp   = lane >> 2;      // 0..7
    const int tig   = lane & 3;       // 0..3
    const int warpM = wid >> 1;       // 0..3  (32-row strip)
    const int warpN = wid & 1;        // 0..1  (64-col strip)
    const int row0  = blockIdx.x * 128;
    const bool relHalf = (blockIdx.y == 0);
    const float* __restrict__ W = relHalf ? Wrel : Wroot;

    const u32 As_u32 = (u32)__cvta_generic_to_shared(As);

    // ---- one-time: load FULL B (128x128) into resident smem ----
    #pragma unroll
    for (int it = 0; it < 16; it++) {
        int idx = tid + it * 256;          // 0..4095 float4s
        int kr  = idx >> 5;                // 0..127
        int nq  = idx & 31;                // float4 col
        float4 b = *(const float4*)(W + (size_t)kr * 128 + nq * 4);
        int base = kr * BSTR + nq * 4;     // odd stride -> scalar stores
        Bs[base + 0] = b.x;
        Bs[base + 1] = b.y;
        Bs[base + 2] = b.z;
        Bs[base + 3] = b.w;
    }

    // ---- prefetch A tile 0 ----
    {
        #pragma unroll
        for (int j = 0; j < 2; j++) {
            int idx = tid + j * 256;
            int r   = idx >> 2;
            int kq  = idx & 3;
            int gr  = row0 + r;
            int ok  = (gr < M);
            const float* src = A + (size_t)(ok ? gr : 0) * 128 + kq * 4;
            u32 dst = As_u32 + (u32)(r * ASTR + kq * 4) * 4u;
            cp_async16(dst, src, ok ? 16 : 0);
        }
        cp_async_commit();
    }

    float acc[2][8][4];
    #pragma unroll
    for (int mt = 0; mt < 2; mt++)
        #pragma unroll
        for (int nt = 0; nt < 8; nt++)
            #pragma unroll
            for (int c = 0; c < 4; c++) acc[mt][nt][c] = 0.f;

    for (int kt = 0; kt < 8; kt++) {
        const int k0  = kt * 16;
        const int buf = kt & 1;

        cp_async_wait0();
        __syncthreads();   // A tile ready; orders B STS (iter 0) and buffer reuse

        // prefetch next A tile into the other buffer
        if (kt < 7) {
            int nk0 = k0 + 16;
            #pragma unroll
            for (int j = 0; j < 2; j++) {
                int idx = tid + j * 256;
                int r   = idx >> 2;
                int kq  = idx & 3;
                int gr  = row0 + r;
                int ok  = (gr < M);
                const float* src = A + (size_t)(ok ? gr : 0) * 128 + nk0 + kq * 4;
                u32 dst = As_u32 + (u32)(((buf ^ 1) * A_TILE) + r * ASTR + kq * 4) * 4u;
                cp_async16(dst, src, ok ? 16 : 0);
            }
            cp_async_commit();
        }

        const float* Ab = As + buf * A_TILE;

        #pragma unroll
        for (int ks = 0; ks < 2; ks++) {
            const int k = ks * 8;
            u32 ah[2][4], al[2][4], bh[8][2], bl[8][2];
            #pragma unroll
            for (int mt = 0; mt < 2; mt++) {
                int m  = warpM * 32 + mt * 16 + grp;
                int b0 = m * ASTR + k + tig;
                float f0 = Ab[b0];
                float f1 = Ab[b0 + 8 * ASTR];
                float f2 = Ab[b0 + 4];
                float f3 = Ab[b0 + 8 * ASTR + 4];
                if (RELU) {
                    f0 = fmaxf(f0, 0.f); f1 = fmaxf(f1, 0.f);
                    f2 = fmaxf(f2, 0.f); f3 = fmaxf(f3, 0.f);
                }
                split_tf32(f0, ah[mt][0], al[mt][0]);
                split_tf32(f1, ah[mt][1], al[mt][1]);
                split_tf32(f2, ah[mt][2], al[mt][2]);
                split_tf32(f3, ah[mt][3], al[mt][3]);
            }
            #pragma unroll
            for (int nt = 0; nt < 8; nt++) {
                int n  = warpN * 64 + nt * 8 + grp;
                int b0 = (k0 + k + tig) * BSTR + n;
                float f0 = Bs[b0];
                float f1 = Bs[b0 + 4 * BSTR];
                split_tf32(f0, bh[nt][0], bl[nt][0]);
                split_tf32(f1, bh[nt][1], bl[nt][1]);
            }
            #pragma unroll
            for (int mt = 0; mt < 2; mt++)
                #pragma unroll
                for (int nt = 0; nt < 8; nt++) {
                    mma_tf32(acc[mt][nt], ah[mt], bh[nt]);   // hi*hi
                    mma_tf32(acc[mt][nt], ah[mt], bl[nt]);   // hi*lo
                    mma_tf32(acc[mt][nt], al[mt], bh[nt]);   // lo*hi
                }
        }
        __syncthreads();   // all reads of buf done before next prefetch overwrites
    }

    // ---- epilogue ----
    #pragma unroll
    for (int mt = 0; mt < 2; mt++) {
        int r0 = row0 + warpM * 32 + mt * 16 + grp;
        int r1 = r0 + 8;
        #pragma unroll
        for (int nt = 0; nt < 8; nt++) {
            int c = warpN * 64 + nt * 8 + 2 * tig;   // 0..126
            if (relHalf) {
                if (r0 < M) *(float2*)(Z + (size_t)r0 * 128 + c) =
                    make_float2(acc[mt][nt][0], acc[mt][nt][1]);
                if (r1 < M) *(float2*)(Z + (size_t)r1 * 128 + c) =
                    make_float2(acc[mt][nt][2], acc[mt][nt][3]);
            } else {
                float bx = bias[c], by = bias[c + 1];
                if (r0 < M) *(float2*)(H + (size_t)r0 * 128 + c) =
                    make_float2(acc[mt][nt][0] + bx, acc[mt][nt][1] + by);
                if (r1 < M) *(float2*)(H + (size_t)r1 * 128 + c) =
                    make_float2(acc[mt][nt][2] + bx, acc[mt][nt][3] + by);
            }
        }
    }
}

// ---------------------------------------------------------------------------
// CSR gather: one warp per dst node, 8-way unrolled, no atomics.
// ---------------------------------------------------------------------------
__global__ void __launch_bounds__(256)
gather_kernel(const float* __restrict__ Z,
              float* __restrict__ H,
              int Nn)
{
    int warp = (int)((blockIdx.x * (unsigned)blockDim.x + threadIdx.x) >> 5);
    int lane = threadIdx.x & 31;
    if (warp >= Nn) return;

    int lo = g_off[warp];
    int hi = g_off[warp + 1];
    if (lo == hi) return;

    float4 acc = make_float4(0.f, 0.f, 0.f, 0.f);
    int e = lo;
    for (; e + 7 < hi; e += 8) {
        int   s[8]; float w[8]; float4 v[8];
        #pragma unroll
        for (int j = 0; j < 8; j++) { s[j] = g_src[e + j]; w[j] = g_wp[e + j]; }
        #pragma unroll
        for (int j = 0; j < 8; j++)
            v[j] = ((const float4*)(Z + (size_t)s[j] * 128))[lane];
        #pragma unroll
        for (int j = 0; j < 8; j++) {
            acc.x = fmaf(w[j], v[j].x, acc.x);
            acc.y = fmaf(w[j], v[j].y, acc.y);
            acc.z = fmaf(w[j], v[j].z, acc.z);
            acc.w = fmaf(w[j], v[j].w, acc.w);
        }
    }
    for (; e < hi; e++) {
        int   s0 = g_src[e];
        float w0 = g_wp[e];
        float4 v0 = ((const float4*)(Z + (size_t)s0 * 128))[lane];
        acc.x = fmaf(w0, v0.x, acc.x); acc.y = fmaf(w0, v0.y, acc.y);
        acc.z = fmaf(w0, v0.z, acc.z); acc.w = fmaf(w0, v0.w, acc.w);
    }

    float4* hp = ((float4*)(H + (size_t)warp * 128)) + lane;
    float4 h = *hp;
    h.x += acc.x; h.y += acc.y; h.z += acc.z; h.w += acc.w;
    *hp = h;
}

// ---------------------------------------------------------------------------
// Pool + linear + sigmoid; re-zeroes g_deg for the next call.
// ---------------------------------------------------------------------------
__global__ void __launch_bounds__(128)
pool_kernel(const float* __restrict__ H2,
            const float* __restrict__ Wlin,
            const float* __restrict__ blin,
            float* __restrict__ out,
            int Nn)
{
    int g = blockIdx.x;
    int t = threadIdx.x;

    for (int i = g * 128 + t; i < Nn; i += gridDim.x * 128)
        g_deg[i] = 0;

    __shared__ int s_range[2];
    if (t < 2) {
        int target = g + t;
        int lo = 0, hi = Nn;
        while (lo < hi) {
            int mid = (lo + hi) >> 1;
            if (g_batch[mid] < target) lo = mid + 1; else hi = mid;
        }
        s_range[t] = lo;
    }
    __syncthreads();
    int lo = s_range[0], hi = s_range[1];

    float m = -INFINITY;
    for (int n = lo; n < hi; n++)
        m = fmaxf(m, H2[(size_t)n * 128 + t]);
    if (hi > lo) m = fmaxf(m, 0.0f);

    float v = m * Wlin[t];

    __shared__ float red[128];
    red[t] = v;
    __syncthreads();
    #pragma unroll
    for (int s = 64; s > 0; s >>= 1) {
        if (t < s) red[t] += red[t + s];
        __syncthreads();
    }
    if (t == 0) {
        float logit = red[0] + blin[0];
        out[g] = 1.0f / (1.0f + expf(-logit));
    }
}

// ---------------------------------------------------------------------------
extern "C" void kernel_launch(void* const* d_in, const int* in_sizes, int n_in,
                              void* d_out, int out_size)
{
    const float* x      = (const float*) d_in[0];
    const int*   ei     = (const int*)   d_in[1];
    const int*   batch  = (const int*)   d_in[2];
    const float* ew     = (const float*) d_in[3];
    const float* W1rel  = (const float*) d_in[4];
    const float* b1     = (const float*) d_in[5];
    const float* W1root = (const float*) d_in[6];
    const float* W2rel  = (const float*) d_in[7];
    const float* b2     = (const float*) d_in[8];
    const float* W2root = (const float*) d_in[9];
    const float* Wlin   = (const float*) d_in[10];
    const float* blin   = (const float*) d_in[11];
    float* out = (float*)d_out;

    int M = in_sizes[0] / 128;
    int E = in_sizes[1] / 2;
    int G = out_size;
    if (M > MAX_NODES) M = MAX_NODES;
    if (E > MAX_EDGES) E = MAX_EDGES;

    float *Z, *H1, *H2;
    cudaGetSymbolAddress((void**)&Z,  g_Z);
    cudaGetSymbolAddress((void**)&H1, g_H1);
    cudaGetSymbolAddress((void**)&H2, g_H2);

    // Allow >48KB dynamic smem for the GEMM.  Idempotent host-side attribute
    // registration (not a stream op; safe under graph capture; no static guard).
    cudaFuncSetAttribute(gemm_dual<false>,
        cudaFuncAttributeMaxDynamicSharedMemorySize, GEMM_SMEM_BYTES);
    cudaFuncSetAttribute(gemm_dual<true>,
        cudaFuncAttributeMaxDynamicSharedMemorySize, GEMM_SMEM_BYTES);

    int NB = (M + SCAN_CHUNK - 1) / SCAN_CHUNK;
    dim3 ggrid((M + 127) / 128, 2);
    int gatherBlocks = (M * 32 + 255) / 256;

    // 1: convert + detect + histogram
    {
        int work = 2 * E;
        if (M > work) work = M;
        convert_hist<<<(work + 255) / 256, 256>>>(ei, batch, E, M);
    }
    // 2-3: scan front half
    partial_kernel  <<<NB, 256>>>(M);
    scan_part_kernel<<<1, 64>>>(NB, M);
    // 4: Layer-1 GEMM (no CSR dependence) -- profiled launch
    gemm_dual<false><<<ggrid, 256, GEMM_SMEM_BYTES>>>(x, W1rel, W1root, b1, Z, H1, M);
    // 5-6: finish CSR build
    writeoff_kernel <<<NB, 256>>>(M);
    fill_kernel<<<(E + 255) / 256, 256>>>(ew, E, M);
    // 7: Layer-1 gather
    gather_kernel<<<gatherBlocks, 256>>>(Z, H1, M);
    // 8-9: Layer 2
    gemm_dual<true><<<ggrid, 256, GEMM_SMEM_BYTES>>>(H1, W2rel, W2root, b2, Z, H2, M);
    gather_kernel<<<gatherBlocks, 256>>>(Z, H2, M);
    // 10: Pool + linear + sigmoid (+ deg re-zero)
    pool_kernel<<<G, 128>>>(H2, Wlin, blin, out, M);
}